// round 7
// baseline (speedup 1.0000x reference)
#include <cuda_runtime.h>
#include <cuda_bf16.h>
#include <math.h>
#include <stdint.h>

#define T_   1024
#define HID_ 5120
#define NH_  128
#define DN_  128
#define DR_  64
#define DV_  128
#define QLR_ 1536
#define KVLR_ 512
#define DQK_ 192    // DN+DR
#define DKV_ 256    // DN+DV
#define NQKV_ 2112  // QLR+KVLR+DR
#define NQKV_PAD_ 2176

// ---------------- fp32 scratch ----------------------------------------------
__device__ float g_qkv [T_ * NQKV_PAD_];
__device__ float g_v   [T_ * NH_ * DV_];
__device__ float g_cos [T_ * 32];
__device__ float g_sin [T_ * 32];

// ---------------- bf16 split scratch ----------------------------------------
__device__ __nv_bfloat16 g_w1h[NQKV_PAD_ * HID_];
__device__ __nv_bfloat16 g_w1l[NQKV_PAD_ * HID_];
__device__ __nv_bfloat16 g_w2h[(NH_*DQK_) * QLR_];
__device__ __nv_bfloat16 g_w2l[(NH_*DQK_) * QLR_];
__device__ __nv_bfloat16 g_w3h[(NH_*DKV_) * KVLR_];
__device__ __nv_bfloat16 g_w3l[(NH_*DKV_) * KVLR_];
__device__ __nv_bfloat16 g_w4h[HID_ * (NH_*DV_)];
__device__ __nv_bfloat16 g_w4l[HID_ * (NH_*DV_)];
__device__ __nv_bfloat16 g_ah [T_ * (NH_*DV_)];
__device__ __nv_bfloat16 g_al [T_ * (NH_*DV_)];
__device__ __nv_bfloat16 g_qanh[T_ * QLR_], g_qanl[T_ * QLR_];
__device__ __nv_bfloat16 g_kvanh[T_ * KVLR_], g_kvanl[T_ * KVLR_];
__device__ __nv_bfloat16 g_qh[T_ * NH_ * DQK_], g_ql[T_ * NH_ * DQK_];
__device__ __nv_bfloat16 g_kh[T_ * NH_ * DQK_], g_kl[T_ * NH_ * DQK_];
__device__ __nv_bfloat16 g_vth[NH_ * DV_ * T_], g_vtl[NH_ * DV_ * T_];  // [h][d][t]

// ======================= PTX helpers =========================================
__device__ __forceinline__ uint32_t smem_u32(const void* p) {
    uint32_t a;
    asm("{ .reg .u64 t; cvta.to.shared.u64 t, %1; cvt.u32.u64 %0, t; }" : "=r"(a) : "l"(p));
    return a;
}

#define CP_ASYNC16(dst_u32, src_ptr) \
    asm volatile("cp.async.cg.shared.global [%0], [%1], 16;" :: "r"(dst_u32), "l"(src_ptr))
#define CP_COMMIT() asm volatile("cp.async.commit_group;" ::: "memory")
#define CP_WAIT1()  asm volatile("cp.async.wait_group 1;" ::: "memory")
#define CP_WAIT0()  asm volatile("cp.async.wait_group 0;" ::: "memory")

#define LDSM_X4(r0, r1, r2, r3, addr) \
    asm volatile("ldmatrix.sync.aligned.m8n8.x4.shared.b16 {%0,%1,%2,%3}, [%4];" \
        : "=r"(r0), "=r"(r1), "=r"(r2), "=r"(r3) : "r"(addr))
#define LDSM_X2(r0, r1, addr) \
    asm volatile("ldmatrix.sync.aligned.m8n8.x2.shared.b16 {%0,%1}, [%2];" \
        : "=r"(r0), "=r"(r1) : "r"(addr))

#define MMA16816(d, a, b) \
    asm volatile("mma.sync.aligned.m16n8k16.row.col.f32.bf16.bf16.f32 " \
        "{%0,%1,%2,%3},{%4,%5,%6,%7},{%8,%9},{%0,%1,%2,%3};" \
        : "+f"((d)[0]), "+f"((d)[1]), "+f"((d)[2]), "+f"((d)[3]) \
        : "r"((a)[0]), "r"((a)[1]), "r"((a)[2]), "r"((a)[3]), "r"((b)[0]), "r"((b)[1]))

// ======================= bf16 split conversion ===============================
__device__ __forceinline__ void split2(float v, __nv_bfloat16& h, __nv_bfloat16& l) {
    h = __float2bfloat16_rn(v);
    l = __float2bfloat16_rn(v - __bfloat162float(h));
}
__device__ __forceinline__ uint32_t pack2(__nv_bfloat16 a, __nv_bfloat16 b) {
    __nv_bfloat162 t(a, b);
    return *(uint32_t*)&t;
}

__global__ void convA4_kernel(const float* __restrict__ A,
                              __nv_bfloat16* __restrict__ H,
                              __nv_bfloat16* __restrict__ L, int n4) {
    int i = blockIdx.x * blockDim.x + threadIdx.x;
    if (i < n4) {
        float4 v = ((const float4*)A)[i];
        __nv_bfloat16 h0,l0,h1,l1,h2,l2,h3,l3;
        split2(v.x,h0,l0); split2(v.y,h1,l1); split2(v.z,h2,l2); split2(v.w,h3,l3);
        uint2 uh, ul;
        uh.x = pack2(h0,h1); uh.y = pack2(h2,h3);
        ul.x = pack2(l0,l1); ul.y = pack2(l2,l3);
        ((uint2*)H)[i] = uh; ((uint2*)L)[i] = ul;
    }
}

__global__ void convBT_kernel(const float* __restrict__ B,
                              __nv_bfloat16* __restrict__ TH,
                              __nv_bfloat16* __restrict__ TL,
                              int K, int N) {
    __shared__ float tile[64][65];
    const int k0 = blockIdx.x * 64, n0 = blockIdx.y * 64;
    const int tid = threadIdx.x; // 256
    for (int i = tid; i < 64 * 16; i += 256) {
        const int r = i >> 4, c4 = (i & 15) * 4;
        const int n = n0 + c4;
        float4 v = make_float4(0.f, 0.f, 0.f, 0.f);
        if (n < N) v = *(const float4*)(B + (size_t)(k0 + r) * N + n);
        tile[r][c4 + 0] = v.x; tile[r][c4 + 1] = v.y;
        tile[r][c4 + 2] = v.z; tile[r][c4 + 3] = v.w;
    }
    __syncthreads();
    for (int i = tid; i < 64 * 16; i += 256) {
        const int nr = i >> 4, kg = (i & 15) * 4;
        __nv_bfloat16 h0,l0,h1,l1,h2,l2,h3,l3;
        split2(tile[kg + 0][nr], h0, l0);
        split2(tile[kg + 1][nr], h1, l1);
        split2(tile[kg + 2][nr], h2, l2);
        split2(tile[kg + 3][nr], h3, l3);
        uint2 uh, ul;
        uh.x = pack2(h0,h1); uh.y = pack2(h2,h3);
        ul.x = pack2(l0,l1); ul.y = pack2(l2,l3);
        const size_t off = (size_t)(n0 + nr) * K + k0 + kg;
        *(uint2*)(TH + off) = uh;
        *(uint2*)(TL + off) = ul;
    }
}

// ======================= HMMA split GEMM (split-K capable) ===================
#define GPITCH 80
#define GTILE  (128 * GPITCH)
#define GSTAGE (4 * GTILE)
#define GEMM_SMEM (2 * GSTAGE)

__global__ void __launch_bounds__(256, 2)
gemm_hmma(const __nv_bfloat16* __restrict__ Ah, const __nv_bfloat16* __restrict__ Al,
          const __nv_bfloat16* __restrict__ Bh, const __nv_bfloat16* __restrict__ Bl,
          float* __restrict__ C, int Nreal, int ldC, int K, int mode,
          __nv_bfloat16* __restrict__ outH, __nv_bfloat16* __restrict__ outL,
          float* __restrict__ vout) {
    extern __shared__ char smem[];
    const uint32_t sb = smem_u32(smem);
    const int tid  = threadIdx.x;
    const int wid  = tid >> 5;
    const int lane = tid & 31;
    const int wm   = wid & 1;
    const int wn   = wid >> 1;
    const int bm   = blockIdx.y * 128;
    const int bn   = blockIdx.x * 128;
    const int nsplit = gridDim.z;
    const int Kpart = K / nsplit;
    const int kbase = blockIdx.z * Kpart;
    const int nchunks = Kpart >> 5;

    const int r0c = tid >> 2, c40 = (tid & 3);

    auto issue = [&](int stage, int c) {
        const int k0 = kbase + (c << 5);
        const uint32_t st = sb + stage * GSTAGE;
#pragma unroll
        for (int p = 0; p < 2; p++) {
            const int row = r0c + p * 64;
            const uint32_t doff = row * GPITCH + c40 * 16;
            const size_t goA = (size_t)(bm + row) * K + k0 + c40 * 8;
            const size_t goB = (size_t)(bn + row) * K + k0 + c40 * 8;
            CP_ASYNC16(st + 0 * GTILE + doff, Ah + goA);
            CP_ASYNC16(st + 1 * GTILE + doff, Al + goA);
            CP_ASYNC16(st + 2 * GTILE + doff, Bh + goB);
            CP_ASYNC16(st + 3 * GTILE + doff, Bl + goB);
        }
    };

    float acc[4][4][4];
#pragma unroll
    for (int i = 0; i < 4; i++)
#pragma unroll
        for (int j = 0; j < 4; j++)
#pragma unroll
            for (int q = 0; q < 4; q++) acc[i][j][q] = 0.f;

    uint32_t aoff[4], boff[4];
#pragma unroll
    for (int mf = 0; mf < 4; mf++) {
        const int row = wm * 64 + mf * 16 + (lane & 15);
        aoff[mf] = row * GPITCH + ((lane >> 4) & 1) * 16;
    }
#pragma unroll
    for (int nf = 0; nf < 4; nf++) {
        const int row = wn * 32 + nf * 8 + (lane & 7);
        boff[nf] = row * GPITCH + ((lane >> 3) & 1) * 16;
    }

    issue(0, 0);
    CP_COMMIT();
    if (nchunks > 1) issue(1, 1);
    CP_COMMIT();

    for (int c = 0; c < nchunks; c++) {
        CP_WAIT1();
        __syncthreads();
        const uint32_t st = sb + (c & 1) * GSTAGE;
#pragma unroll
        for (int ks = 0; ks < 2; ks++) {
            uint32_t a[4][4], bh[4][2], bl[4][2];
#pragma unroll
            for (int mf = 0; mf < 4; mf++)
                LDSM_X4(a[mf][0], a[mf][1], a[mf][2], a[mf][3],
                        st + 0 * GTILE + aoff[mf] + ks * 32);
#pragma unroll
            for (int nf = 0; nf < 4; nf++) {
                LDSM_X2(bh[nf][0], bh[nf][1], st + 2 * GTILE + boff[nf] + ks * 32);
                LDSM_X2(bl[nf][0], bl[nf][1], st + 3 * GTILE + boff[nf] + ks * 32);
            }
#pragma unroll
            for (int mf = 0; mf < 4; mf++)
#pragma unroll
                for (int nf = 0; nf < 4; nf++) {
                    MMA16816(acc[mf][nf], a[mf], bh[nf]);
                    MMA16816(acc[mf][nf], a[mf], bl[nf]);
                }
#pragma unroll
            for (int mf = 0; mf < 4; mf++)
                LDSM_X4(a[mf][0], a[mf][1], a[mf][2], a[mf][3],
                        st + 1 * GTILE + aoff[mf] + ks * 32);
#pragma unroll
            for (int mf = 0; mf < 4; mf++)
#pragma unroll
                for (int nf = 0; nf < 4; nf++)
                    MMA16816(acc[mf][nf], a[mf], bh[nf]);
        }
        __syncthreads();
        if (c + 2 < nchunks) issue(c & 1, c + 2);
        CP_COMMIT();
    }

    const int lm = lane >> 2, ln = (lane & 3) * 2;
    const float qscale = 0.072168784f; // 1/sqrt(192)
#pragma unroll
    for (int mf = 0; mf < 4; mf++) {
#pragma unroll
        for (int nf = 0; nf < 4; nf++) {
            const int n = bn + wn * 32 + nf * 8 + ln;
            const int m = bm + wm * 64 + mf * 16 + lm;
            if (mode == 0) {
                if (n < Nreal) {
                    float* p0 = C + (size_t)m * ldC + n;
                    float* p1 = C + (size_t)(m + 8) * ldC + n;
                    if (nsplit > 1) {
                        atomicAdd(p0 + 0, acc[mf][nf][0]);
                        atomicAdd(p0 + 1, acc[mf][nf][1]);
                        atomicAdd(p1 + 0, acc[mf][nf][2]);
                        atomicAdd(p1 + 1, acc[mf][nf][3]);
                    } else {
                        p0[0] = acc[mf][nf][0]; p0[1] = acc[mf][nf][1];
                        p1[0] = acc[mf][nf][2]; p1[1] = acc[mf][nf][3];
                    }
                }
            } else if (mode == 1) {
                const int d = n % DQK_;
#pragma unroll
                for (int rr = 0; rr < 2; rr++) {
                    const int mr = m + rr * 8;
                    float x1 = acc[mf][nf][rr * 2 + 0] * qscale;
                    float x2 = acc[mf][nf][rr * 2 + 1] * qscale;
                    if (d >= DN_) {
                        const int j = (d - DN_) >> 1;
                        const float cc = g_cos[mr * 32 + j], ss = g_sin[mr * 32 + j];
                        const float o1 = x1 * cc - x2 * ss, o2 = x2 * cc + x1 * ss;
                        x1 = o1; x2 = o2;
                    }
                    __nv_bfloat16 h0, l0, h1, l1;
                    split2(x1, h0, l0); split2(x2, h1, l1);
                    const size_t off = (size_t)mr * ldC + n;
                    *(uint32_t*)(outH + off) = pack2(h0, h1);
                    *(uint32_t*)(outL + off) = pack2(l0, l1);
                }
            } else { // mode 2
                const int d = n & 255, hh = n >> 8;
#pragma unroll
                for (int rr = 0; rr < 2; rr++) {
                    const int mr = m + rr * 8;
                    const float x1 = acc[mf][nf][rr * 2 + 0];
                    const float x2 = acc[mf][nf][rr * 2 + 1];
                    if (d < DN_) {
                        const size_t off = ((size_t)mr * NH_ + hh) * DQK_ + d;
                        __nv_bfloat16 h0, l0, h1, l1;
                        split2(x1, h0, l0); split2(x2, h1, l1);
                        *(uint32_t*)(outH + off) = pack2(h0, h1);
                        *(uint32_t*)(outL + off) = pack2(l0, l1);
                    } else {
                        const size_t off = ((size_t)mr * NH_ + hh) * DV_ + (d - DN_);
                        *(float2*)(vout + off) = make_float2(x1, x2);
                    }
                }
            }
        }
    }
}

// ======================= rmsnorm (split bf16 output) =========================
__global__ void rmsnorm_split(const float* __restrict__ x, int srcStride, int srcOff, int W,
                              const float* __restrict__ w,
                              __nv_bfloat16* __restrict__ H, __nv_bfloat16* __restrict__ L) {
    const int row = blockIdx.x;
    const float* xr = x + (size_t)row * srcStride + srcOff;
    float ss = 0.f;
    for (int c = threadIdx.x; c < W; c += blockDim.x) {
        float v = xr[c];
        ss += v * v;
    }
    __shared__ float red[32];
#pragma unroll
    for (int o = 16; o; o >>= 1) ss += __shfl_xor_sync(0xffffffffu, ss, o);
    if ((threadIdx.x & 31) == 0) red[threadIdx.x >> 5] = ss;
    __syncthreads();
    if (threadIdx.x < 32) {
        float v = (threadIdx.x < (blockDim.x >> 5)) ? red[threadIdx.x] : 0.f;
#pragma unroll
        for (int o = 16; o; o >>= 1) v += __shfl_xor_sync(0xffffffffu, v, o);
        red[threadIdx.x] = v;
    }
    __syncthreads();
    const float rstd = rsqrtf(red[0] / (float)W + 1e-6f);
    for (int c = threadIdx.x; c < W; c += blockDim.x) {
        __nv_bfloat16 hh, ll;
        split2(xr[c] * rstd * w[c], hh, ll);
        H[(size_t)row * W + c] = hh;
        L[(size_t)row * W + c] = ll;
    }
}

// ======================= RoPE tables + k_pe broadcast ========================
__global__ void rope_tab_kernel(const int* __restrict__ pos) {
    const int t = blockIdx.x, i = threadIdx.x;
    double inv = pow(10000.0, -(double)i / 32.0);
    double f = (double)pos[t] * inv;
    double s, c;
    sincos(f, &s, &c);
    g_cos[t * 32 + i] = (float)c;
    g_sin[t * 32 + i] = (float)s;
}

__global__ void kpe_build_kernel() {
    const int t = blockIdx.x;
    const int i = threadIdx.x;   // pair 0..31
    const int hh = threadIdx.y;  // 0..7
    const float c = g_cos[t * 32 + i];
    const float s = g_sin[t * 32 + i];
    const float* src = g_qkv + (size_t)t * NQKV_PAD_ + (QLR_ + KVLR_) + 2 * i;
    const float x1 = src[0], x2 = src[1];
    const float o1 = x1 * c - x2 * s, o2 = x2 * c + x1 * s;
    __nv_bfloat16 h1, l1, h2, l2;
    split2(o1, h1, l1); split2(o2, h2, l2);
    const uint32_t hv = pack2(h1, h2), lv = pack2(l1, l2);
    for (int h = hh; h < NH_; h += 8) {
        const size_t off = ((size_t)t * NH_ + h) * DQK_ + DN_ + 2 * i;
        *(uint32_t*)(g_kh + off) = hv;
        *(uint32_t*)(g_kl + off) = lv;
    }
}

__global__ void vtrans_kernel() {
    __shared__ float tile[32][33];
    const int t0 = blockIdx.x * 32, d0 = blockIdx.y * 32, h = blockIdx.z;
    const int tx = threadIdx.x, ty = threadIdx.y; // 32 x 8
    for (int i = ty; i < 32; i += 8)
        tile[i][tx] = g_v[((size_t)(t0 + i) * NH_ + h) * DV_ + d0 + tx];
    __syncthreads();
    for (int i = ty; i < 32; i += 8) {
        __nv_bfloat16 hh, ll;
        split2(tile[tx][i], hh, ll);
        const size_t off = ((size_t)h * DV_ + d0 + i) * T_ + t0 + tx;
        g_vth[off] = hh; g_vtl[off] = ll;
    }
}

// ======================= FA2-style HMMA flash attention ======================
// 8 warps: wm = wid&3 (16 q-rows), wn = wid>>2 (S duplicated per wn; O cols
// split 2x64 by wn). Qh fragments register-resident, Ql in smem. S/softmax/P
// entirely in registers (C-frag == A-frag layout identity). K/V via x4 LDSM.
#define QKP 200
#define PVP 72

struct ASmem {
    __nv_bfloat16 Ql[64 * QKP];       // 25.6 KB
    __nv_bfloat16 Kh[64 * QKP];       // 25.6 KB
    __nv_bfloat16 Kl[64 * QKP];       // 25.6 KB
    __nv_bfloat16 VQ[2 * 128 * PVP];  // 36.9 KB: Vh|Vl, initially Qh staging
};
#define ATTN_SMEM sizeof(ASmem)

__global__ void __launch_bounds__(256, 1)
attn_mma() {
    extern __shared__ char smem_raw[];
    ASmem& sm = *(ASmem*)smem_raw;
    const int h = blockIdx.x, qb = blockIdx.y;
    const int tid = threadIdx.x, wid = tid >> 5, lane = tid & 31;
    const int wm = wid & 3, wn = wid >> 2;
    const int t0 = qb * 64;
    const int lm = lane >> 2, ln = (lane & 3) * 2;

    const uint32_t sQl = smem_u32(sm.Ql);
    const uint32_t sKh = smem_u32(sm.Kh), sKl = smem_u32(sm.Kl);
    const uint32_t sVh = smem_u32(sm.VQ);
    const uint32_t sVl = sVh + 128 * PVP * 2;
    const uint32_t sQs = sVh;  // Qh staging (consumed before V loads)

    auto loadK = [&](int kc) {
        const int tk0 = kc * 64;
        for (int idx = tid; idx < 64 * 24; idx += 256) {
            const int row = idx / 24, ch = idx % 24;
            const size_t go = ((size_t)(tk0 + row) * NH_ + h) * DQK_ + ch * 8;
            const uint32_t so = (row * QKP + ch * 8) * 2;
            CP_ASYNC16(sKh + so, g_kh + go);
            CP_ASYNC16(sKl + so, g_kl + go);
        }
    };
    auto loadV = [&](int kc) {
        const int tk0 = kc * 64;
        for (int idx = tid; idx < 128 * 8; idx += 256) {
            const int row = idx >> 3, ch = idx & 7;
            const size_t go = ((size_t)h * DV_ + row) * T_ + tk0 + ch * 8;
            const uint32_t so = (row * PVP + ch * 8) * 2;
            CP_ASYNC16(sVh + so, g_vth + go);
            CP_ASYNC16(sVl + so, g_vtl + go);
        }
    };

    // stage Q (hi to VQ region, lo to Ql)
    for (int idx = tid; idx < 64 * 24; idx += 256) {
        const int row = idx / 24, ch = idx % 24;
        const size_t go = ((size_t)(t0 + row) * NH_ + h) * DQK_ + ch * 8;
        const uint32_t so = (row * QKP + ch * 8) * 2;
        CP_ASYNC16(sQs + so, g_qh + go);
        CP_ASYNC16(sQl + so, g_ql + go);
    }
    CP_COMMIT();
    CP_WAIT0();
    __syncthreads();

    const uint32_t aoffQ = ((wm * 16 + (lane & 15)) * QKP + ((lane >> 4) & 1) * 8) * 2;
    uint32_t qh[12][4];
#pragma unroll
    for (int ks = 0; ks < 12; ks++)
        LDSM_X4(qh[ks][0], qh[ks][1], qh[ks][2], qh[ks][3], sQs + aoffQ + ks * 32);
    __syncthreads();   // Qh staging consumed; VQ region free

    loadK(0); CP_COMMIT();
    loadV(0); CP_COMMIT();

    // K x4 offsets: pair nf = 2j, 2j+1
    uint32_t boffK4[4], boffV4[4];
#pragma unroll
    for (int j = 0; j < 4; j++) {
        const int rowK = j * 16 + ((lane >> 4) & 1) * 8 + (lane & 7);
        boffK4[j] = (rowK * QKP + ((lane >> 3) & 1) * 8) * 2;
        const int rowV = wn * 64 + j * 16 + ((lane >> 4) & 1) * 8 + (lane & 7);
        boffV4[j] = (rowV * PVP + ((lane >> 3) & 1) * 8) * 2;
    }

    float accO[8][4];
#pragma unroll
    for (int i = 0; i < 8; i++)
#pragma unroll
        for (int q = 0; q < 4; q++) accO[i][q] = 0.f;
    float m0 = -1e30f, m1 = -1e30f, l0 = 0.f, l1 = 0.f;

    const int rg0 = t0 + wm * 16 + lm;
    const int rg1 = rg0 + 8;

    for (int kc = 0; kc <= qb; kc++) {
        const int tk0 = kc * 64;
        CP_WAIT1();        // K(kc) ready (V(kc) in flight)
        __syncthreads();

        // ---- S = Q K^T (full 64 cols per warp; duplicated across wn) ----
        float accS[8][4];
#pragma unroll
        for (int i = 0; i < 8; i++)
#pragma unroll
            for (int q = 0; q < 4; q++) accS[i][q] = 0.f;
#pragma unroll
        for (int ks = 0; ks < 12; ks++) {
            uint32_t ql[4];
            LDSM_X4(ql[0], ql[1], ql[2], ql[3], sQl + aoffQ + ks * 32);
#pragma unroll
            for (int j = 0; j < 4; j++) {
                uint32_t kh4[4], kl4[4];
                LDSM_X4(kh4[0], kh4[1], kh4[2], kh4[3], sKh + boffK4[j] + ks * 32);
                LDSM_X4(kl4[0], kl4[1], kl4[2], kl4[3], sKl + boffK4[j] + ks * 32);
                MMA16816(accS[2*j],     qh[ks], kh4);
                MMA16816(accS[2*j + 1], qh[ks], kh4 + 2);
                MMA16816(accS[2*j],     qh[ks], kl4);
                MMA16816(accS[2*j + 1], qh[ks], kl4 + 2);
                MMA16816(accS[2*j],     ql,     kh4);
                MMA16816(accS[2*j + 1], ql,     kh4 + 2);
            }
        }
        __syncthreads();   // K consumed
        if (kc < qb) { loadK(kc + 1); CP_COMMIT(); }

        // ---- mask (diag chunk) ----
        if (kc == qb) {
#pragma unroll
            for (int nf = 0; nf < 8; nf++) {
                const int cg = tk0 + nf * 8 + ln;
                if (cg > rg0)     accS[nf][0] = -1e30f;
                if (cg + 1 > rg0) accS[nf][1] = -1e30f;
                if (cg > rg1)     accS[nf][2] = -1e30f;
                if (cg + 1 > rg1) accS[nf][3] = -1e30f;
            }
        }

        // ---- in-register online softmax (rows rg0, rg1) ----
        float mx0 = -1e30f, mx1 = -1e30f;
#pragma unroll
        for (int nf = 0; nf < 8; nf++) {
            mx0 = fmaxf(mx0, fmaxf(accS[nf][0], accS[nf][1]));
            mx1 = fmaxf(mx1, fmaxf(accS[nf][2], accS[nf][3]));
        }
        mx0 = fmaxf(mx0, __shfl_xor_sync(0xffffffffu, mx0, 1));
        mx0 = fmaxf(mx0, __shfl_xor_sync(0xffffffffu, mx0, 2));
        mx1 = fmaxf(mx1, __shfl_xor_sync(0xffffffffu, mx1, 1));
        mx1 = fmaxf(mx1, __shfl_xor_sync(0xffffffffu, mx1, 2));
        const float mn0 = fmaxf(m0, mx0), mn1 = fmaxf(m1, mx1);
        const float sc0 = __expf(m0 - mn0), sc1 = __expf(m1 - mn1);
        float sum0 = 0.f, sum1 = 0.f;
#pragma unroll
        for (int nf = 0; nf < 8; nf++) {
            accS[nf][0] = __expf(accS[nf][0] - mn0);
            accS[nf][1] = __expf(accS[nf][1] - mn0);
            accS[nf][2] = __expf(accS[nf][2] - mn1);
            accS[nf][3] = __expf(accS[nf][3] - mn1);
            sum0 += accS[nf][0] + accS[nf][1];
            sum1 += accS[nf][2] + accS[nf][3];
        }
        sum0 += __shfl_xor_sync(0xffffffffu, sum0, 1);
        sum0 += __shfl_xor_sync(0xffffffffu, sum0, 2);
        sum1 += __shfl_xor_sync(0xffffffffu, sum1, 1);
        sum1 += __shfl_xor_sync(0xffffffffu, sum1, 2);
        m0 = mn0; m1 = mn1;
        l0 = l0 * sc0 + sum0;
        l1 = l1 * sc1 + sum1;
#pragma unroll
        for (int nf = 0; nf < 8; nf++) {
            accO[nf][0] *= sc0; accO[nf][1] *= sc0;
            accO[nf][2] *= sc1; accO[nf][3] *= sc1;
        }

        // ---- V(kc) ready ----
        if (kc < qb) { CP_WAIT1(); } else { CP_WAIT0(); }
        __syncthreads();

        // ---- O += P V  (P regs, split on the fly) ----
#pragma unroll
        for (int kf = 0; kf < 4; kf++) {
            uint32_t pah[4], pal[4];
#pragma unroll
            for (int half = 0; half < 2; half++) {
                const int nf = 2 * kf + half;
                __nv_bfloat16 h0, e0, h1, e1, h2, e2, h3, e3;
                split2(accS[nf][0], h0, e0);
                split2(accS[nf][1], h1, e1);
                split2(accS[nf][2], h2, e2);
                split2(accS[nf][3], h3, e3);
                pah[2*half + 0] = pack2(h0, h1);
                pah[2*half + 1] = pack2(h2, h3);
                pal[2*half + 0] = pack2(e0, e1);
                pal[2*half + 1] = pack2(e2, e3);
            }
#pragma unroll
            for (int j = 0; j < 4; j++) {
                uint32_t vh4[4], vl4[4];
                LDSM_X4(vh4[0], vh4[1], vh4[2], vh4[3], sVh + boffV4[j] + kf * 32);
                LDSM_X4(vl4[0], vl4[1], vl4[2], vl4[3], sVl + boffV4[j] + kf * 32);
                MMA16816(accO[2*j],     pah, vh4);
                MMA16816(accO[2*j + 1], pah, vh4 + 2);
                MMA16816(accO[2*j],     pah, vl4);
                MMA16816(accO[2*j + 1], pah, vl4 + 2);
                MMA16816(accO[2*j],     pal, vh4);
                MMA16816(accO[2*j + 1], pal, vh4 + 2);
            }
        }
        __syncthreads();   // V consumed
        if (kc < qb) { loadV(kc + 1); CP_COMMIT(); }
    }

    // ---- finalize ----
    const float invL0 = 1.f / l0, invL1 = 1.f / l1;
#pragma unroll
    for (int nf = 0; nf < 8; nf++) {
        const int col = h * DV_ + wn * 64 + nf * 8 + ln;
        __nv_bfloat16 h0, e0, h1, e1;
        split2(accO[nf][0] * invL0, h0, e0);
        split2(accO[nf][1] * invL0, h1, e1);
        *(uint32_t*)(g_ah + (size_t)rg0 * (NH_ * DV_) + col) = pack2(h0, h1);
        *(uint32_t*)(g_al + (size_t)rg0 * (NH_ * DV_) + col) = pack2(e0, e1);
        split2(accO[nf][2] * invL1, h0, e0);
        split2(accO[nf][3] * invL1, h1, e1);
        *(uint32_t*)(g_ah + (size_t)rg1 * (NH_ * DV_) + col) = pack2(h0, h1);
        *(uint32_t*)(g_al + (size_t)rg1 * (NH_ * DV_) + col) = pack2(e0, e1);
    }
}

// ======================= launch ==============================================
extern "C" void kernel_launch(void* const* d_in, const int* in_sizes, int n_in,
                              void* d_out, int out_size) {
    const int*   positions = (const int*)d_in[0];
    const float* hidden    = (const float*)d_in[1];
    const float* w_qkv_a   = (const float*)d_in[2];
    const float* q_a_ln_w  = (const float*)d_in[3];
    const float* w_q_b     = (const float*)d_in[4];
    const float* kv_a_ln_w = (const float*)d_in[5];
    const float* w_kv_b    = (const float*)d_in[6];
    const float* w_o       = (const float*)d_in[7];
    float* out = (float*)d_out;

    float *p_qkv, *p_v;
    cudaGetSymbolAddress((void**)&p_qkv, g_qkv);
    cudaGetSymbolAddress((void**)&p_v,   g_v);

    __nv_bfloat16 *w1h, *w1l, *w2h, *w2l, *w3h, *w3l, *w4h, *w4l, *ah, *al;
    __nv_bfloat16 *qanh, *qanl, *kvanh, *kvanl, *qh, *ql, *kh, *kl;
    cudaGetSymbolAddress((void**)&w1h, g_w1h); cudaGetSymbolAddress((void**)&w1l, g_w1l);
    cudaGetSymbolAddress((void**)&w2h, g_w2h); cudaGetSymbolAddress((void**)&w2l, g_w2l);
    cudaGetSymbolAddress((void**)&w3h, g_w3h); cudaGetSymbolAddress((void**)&w3l, g_w3l);
    cudaGetSymbolAddress((void**)&w4h, g_w4h); cudaGetSymbolAddress((void**)&w4l, g_w4l);
    cudaGetSymbolAddress((void**)&ah,  g_ah);  cudaGetSymbolAddress((void**)&al,  g_al);
    cudaGetSymbolAddress((void**)&qanh, g_qanh); cudaGetSymbolAddress((void**)&qanl, g_qanl);
    cudaGetSymbolAddress((void**)&kvanh, g_kvanh); cudaGetSymbolAddress((void**)&kvanl, g_kvanl);
    cudaGetSymbolAddress((void**)&qh, g_qh); cudaGetSymbolAddress((void**)&ql, g_ql);
    cudaGetSymbolAddress((void**)&kh, g_kh); cudaGetSymbolAddress((void**)&kl, g_kl);

    cudaFuncSetAttribute(gemm_hmma, cudaFuncAttributeMaxDynamicSharedMemorySize, GEMM_SMEM);
    cudaFuncSetAttribute(attn_mma, cudaFuncAttributeMaxDynamicSharedMemorySize, (int)ATTN_SMEM);

    rope_tab_kernel<<<T_, 32>>>(positions);

    convBT_kernel<<<dim3(HID_ / 64, NQKV_PAD_ / 64), 256>>>(w_qkv_a, w1h, w1l, HID_, NQKV_);
    convBT_kernel<<<dim3(QLR_ / 64, (NH_ * DQK_) / 64), 256>>>(w_q_b, w2h, w2l, QLR_, NH_ * DQK_);
    convBT_kernel<<<dim3(KVLR_ / 64, (NH_ * DKV_) / 64), 256>>>(w_kv_b, w3h, w3l, KVLR_, NH_ * DKV_);
    convBT_kernel<<<dim3((NH_ * DV_) / 64, HID_ / 64), 256>>>(w_o, w4h, w4l, NH_ * DV_, HID_);

    // GEMM1 (split-K=2, atomic accumulate) — zero destination first
    cudaMemsetAsync(p_qkv, 0, (size_t)T_ * NQKV_PAD_ * sizeof(float));
    convA4_kernel<<<(T_ * HID_ / 4 + 255) / 256, 256>>>(hidden, ah, al, T_ * HID_ / 4);
    gemm_hmma<<<dim3(NQKV_PAD_ / 128, T_ / 128, 2), 256, GEMM_SMEM>>>(
        ah, al, w1h, w1l, p_qkv, NQKV_, NQKV_PAD_, HID_, 0, nullptr, nullptr, nullptr);

    rmsnorm_split<<<T_, 256>>>(p_qkv, NQKV_PAD_, 0,    QLR_,  q_a_ln_w,  qanh,  qanl);
    rmsnorm_split<<<T_, 256>>>(p_qkv, NQKV_PAD_, QLR_, KVLR_, kv_a_ln_w, kvanh, kvanl);

    gemm_hmma<<<dim3((NH_ * DQK_) / 128, T_ / 128), 256, GEMM_SMEM>>>(
        qanh, qanl, w2h, w2l, nullptr, NH_ * DQK_, NH_ * DQK_, QLR_, 1, qh, ql, nullptr);
    gemm_hmma<<<dim3((NH_ * DKV_) / 128, T_ / 128), 256, GEMM_SMEM>>>(
        kvanh, kvanl, w3h, w3l, nullptr, NH_ * DKV_, NH_ * DKV_, KVLR_, 2, kh, kl, p_v);

    kpe_build_kernel<<<T_, dim3(32, 8)>>>();
    vtrans_kernel<<<dim3(T_ / 32, DV_ / 32, NH_), dim3(32, 8)>>>();

    attn_mma<<<dim3(NH_, T_ / 64), 256, ATTN_SMEM>>>();

    gemm_hmma<<<dim3(HID_ / 128, T_ / 128), 256, GEMM_SMEM>>>(
        ah, al, w4h, w4l, out, HID_, HID_, NH_ * DV_, 0, nullptr, nullptr, nullptr);
}

// round 8
// speedup vs baseline: 2.4785x; 2.4785x over previous
#include <cuda_runtime.h>
#include <cuda_fp16.h>
#include <math.h>
#include <stdint.h>

#define T_   1024
#define HID_ 5120
#define NH_  128
#define DN_  128
#define DR_  64
#define DV_  128
#define QLR_ 1536
#define KVLR_ 512
#define DQK_ 192    // DN+DR
#define DKV_ 256    // DN+DV
#define NQKV_ 2112  // QLR+KVLR+DR
#define NQKV_PAD_ 2304

// ---------------- fp32 scratch ----------------------------------------------
__device__ float g_qkv [T_ * NQKV_];
__device__ float g_v   [T_ * NH_ * DV_];
__device__ float g_cos [T_ * 32];
__device__ float g_sin [T_ * 32];

// ---------------- fp16 scratch ----------------------------------------------
__device__ __half g_w1[NQKV_PAD_ * HID_];
__device__ __half g_w2[(NH_*DQK_) * QLR_];
__device__ __half g_w3[(NH_*DKV_) * KVLR_];
__device__ __half g_w4[HID_ * (NH_*DV_)];
__device__ __half g_a [T_ * (NH_*DV_)];        // A buf: hidden conv, then attn out
__device__ __half g_qan[T_ * QLR_];
__device__ __half g_kvan[T_ * KVLR_];
__device__ __half g_qh[T_ * NH_ * DQK_];
__device__ __half g_kh[T_ * NH_ * DQK_];
__device__ __half g_vt[NH_ * DV_ * T_];        // [h][d][t]

// ======================= PTX helpers =========================================
__device__ __forceinline__ uint32_t smem_u32(const void* p) {
    uint32_t a;
    asm("{ .reg .u64 t; cvta.to.shared.u64 t, %1; cvt.u32.u64 %0, t; }" : "=r"(a) : "l"(p));
    return a;
}

#define CP_ASYNC16(dst_u32, src_ptr) \
    asm volatile("cp.async.cg.shared.global [%0], [%1], 16;" :: "r"(dst_u32), "l"(src_ptr))
#define CP_COMMIT() asm volatile("cp.async.commit_group;" ::: "memory")
#define CP_WAIT1()  asm volatile("cp.async.wait_group 1;" ::: "memory")
#define CP_WAIT0()  asm volatile("cp.async.wait_group 0;" ::: "memory")

#define LDSM_X4(r0, r1, r2, r3, addr) \
    asm volatile("ldmatrix.sync.aligned.m8n8.x4.shared.b16 {%0,%1,%2,%3}, [%4];" \
        : "=r"(r0), "=r"(r1), "=r"(r2), "=r"(r3) : "r"(addr))
#define LDSM_X2(r0, r1, addr) \
    asm volatile("ldmatrix.sync.aligned.m8n8.x2.shared.b16 {%0,%1}, [%2];" \
        : "=r"(r0), "=r"(r1) : "r"(addr))

#define MMA16816(d, a, b) \
    asm volatile("mma.sync.aligned.m16n8k16.row.col.f32.f16.f16.f32 " \
        "{%0,%1,%2,%3},{%4,%5,%6,%7},{%8,%9},{%0,%1,%2,%3};" \
        : "+f"((d)[0]), "+f"((d)[1]), "+f"((d)[2]), "+f"((d)[3]) \
        : "r"((a)[0]), "r"((a)[1]), "r"((a)[2]), "r"((a)[3]), "r"((b)[0]), "r"((b)[1]))

// ======================= fp16 conversion =====================================
__device__ __forceinline__ uint32_t pack2h(__half a, __half b) {
    __half2 t(a, b);
    return *(uint32_t*)&t;
}

__global__ void convA4_kernel(const float* __restrict__ A,
                              __half* __restrict__ H, int n4) {
    int i = blockIdx.x * blockDim.x + threadIdx.x;
    if (i < n4) {
        float4 v = ((const float4*)A)[i];
        uint2 uh;
        uh.x = pack2h(__float2half_rn(v.x), __float2half_rn(v.y));
        uh.y = pack2h(__float2half_rn(v.z), __float2half_rn(v.w));
        ((uint2*)H)[i] = uh;
    }
}

// B [K,N] fp32 -> Bt [Npad,K] fp16 (transpose), 64x64 tiles
__global__ void convBT_kernel(const float* __restrict__ B,
                              __half* __restrict__ TH, int K, int N) {
    __shared__ float tile[64][65];
    const int k0 = blockIdx.x * 64, n0 = blockIdx.y * 64;
    const int tid = threadIdx.x; // 256
    for (int i = tid; i < 64 * 16; i += 256) {
        const int r = i >> 4, c4 = (i & 15) * 4;
        const int n = n0 + c4;
        float4 v = make_float4(0.f, 0.f, 0.f, 0.f);
        if (n < N) v = *(const float4*)(B + (size_t)(k0 + r) * N + n);
        tile[r][c4 + 0] = v.x; tile[r][c4 + 1] = v.y;
        tile[r][c4 + 2] = v.z; tile[r][c4 + 3] = v.w;
    }
    __syncthreads();
    for (int i = tid; i < 64 * 16; i += 256) {
        const int nr = i >> 4, kg = (i & 15) * 4;
        uint2 uh;
        uh.x = pack2h(__float2half_rn(tile[kg + 0][nr]), __float2half_rn(tile[kg + 1][nr]));
        uh.y = pack2h(__float2half_rn(tile[kg + 2][nr]), __float2half_rn(tile[kg + 3][nr]));
        *(uint2*)(TH + (size_t)(n0 + nr) * K + k0 + kg) = uh;
    }
}

// ======================= fp16 HMMA GEMM with fused epilogues =================
// C[M,N] = A[M,K] @ B^T[N,K], fp16 inputs, fp32 accum.
// mode 0: C fp32 (guard n<Nreal)
// mode 1: q path  — scale 1/sqrt(192), RoPE on d>=128 -> outH fp16
// mode 2: kv path — d<128: k fp16 -> outH [t][h*192+d]; d>=128: fp32 V -> vout
#define GPITCH 80
#define GTILE  (128 * GPITCH)
#define GSTAGE (2 * GTILE)
#define GEMM_SMEM (2 * GSTAGE)   // 40960 B

__global__ void __launch_bounds__(256, 2)
gemm_hmma(const __half* __restrict__ A, const __half* __restrict__ B,
          float* __restrict__ C, int Nreal, int ldC, int K, int mode,
          __half* __restrict__ outH, float* __restrict__ vout) {
    extern __shared__ char smem[];
    const uint32_t sb = smem_u32(smem);
    const int tid  = threadIdx.x;
    const int wid  = tid >> 5;
    const int lane = tid & 31;
    const int wm   = wid & 1;
    const int wn   = wid >> 1;
    const int bm   = blockIdx.y * 128;
    const int bn   = blockIdx.x * 128;
    const int nchunks = K >> 5;

    const int r0c = tid >> 2, c40 = (tid & 3);

    auto issue = [&](int stage, int c) {
        const int k0 = c << 5;
        const uint32_t st = sb + stage * GSTAGE;
#pragma unroll
        for (int p = 0; p < 2; p++) {
            const int row = r0c + p * 64;
            const uint32_t doff = row * GPITCH + c40 * 16;
            CP_ASYNC16(st + doff,         A + (size_t)(bm + row) * K + k0 + c40 * 8);
            CP_ASYNC16(st + GTILE + doff, B + (size_t)(bn + row) * K + k0 + c40 * 8);
        }
    };

    float acc[4][4][4];
#pragma unroll
    for (int i = 0; i < 4; i++)
#pragma unroll
        for (int j = 0; j < 4; j++)
#pragma unroll
            for (int q = 0; q < 4; q++) acc[i][j][q] = 0.f;

    uint32_t aoff[4], boff[4];
#pragma unroll
    for (int mf = 0; mf < 4; mf++) {
        const int row = wm * 64 + mf * 16 + (lane & 15);
        aoff[mf] = row * GPITCH + ((lane >> 4) & 1) * 16;
    }
#pragma unroll
    for (int nf = 0; nf < 4; nf++) {
        const int row = wn * 32 + nf * 8 + (lane & 7);
        boff[nf] = row * GPITCH + ((lane >> 3) & 1) * 16;
    }

    issue(0, 0);
    CP_COMMIT();
    if (nchunks > 1) issue(1, 1);
    CP_COMMIT();

    for (int c = 0; c < nchunks; c++) {
        CP_WAIT1();
        __syncthreads();
        const uint32_t st = sb + (c & 1) * GSTAGE;
#pragma unroll
        for (int ks = 0; ks < 2; ks++) {
            uint32_t a[4][4], b[4][2];
#pragma unroll
            for (int mf = 0; mf < 4; mf++)
                LDSM_X4(a[mf][0], a[mf][1], a[mf][2], a[mf][3],
                        st + aoff[mf] + ks * 32);
#pragma unroll
            for (int nf = 0; nf < 4; nf++)
                LDSM_X2(b[nf][0], b[nf][1], st + GTILE + boff[nf] + ks * 32);
#pragma unroll
            for (int mf = 0; mf < 4; mf++)
#pragma unroll
                for (int nf = 0; nf < 4; nf++)
                    MMA16816(acc[mf][nf], a[mf], b[nf]);
        }
        __syncthreads();
        if (c + 2 < nchunks) issue(c & 1, c + 2);
        CP_COMMIT();
    }

    const int lm = lane >> 2, ln = (lane & 3) * 2;
    const float qscale = 0.072168784f; // 1/sqrt(192)
#pragma unroll
    for (int mf = 0; mf < 4; mf++) {
#pragma unroll
        for (int nf = 0; nf < 4; nf++) {
            const int n = bn + wn * 32 + nf * 8 + ln;
            const int m = bm + wm * 64 + mf * 16 + lm;
            if (mode == 0) {
                if (n < Nreal) {
                    float* p0 = C + (size_t)m * ldC + n;
                    float* p1 = C + (size_t)(m + 8) * ldC + n;
                    p0[0] = acc[mf][nf][0]; p0[1] = acc[mf][nf][1];
                    p1[0] = acc[mf][nf][2]; p1[1] = acc[mf][nf][3];
                }
            } else if (mode == 1) {
                const int d = n % DQK_;
#pragma unroll
                for (int rr = 0; rr < 2; rr++) {
                    const int mr = m + rr * 8;
                    float x1 = acc[mf][nf][rr * 2 + 0] * qscale;
                    float x2 = acc[mf][nf][rr * 2 + 1] * qscale;
                    if (d >= DN_) {
                        const int j = (d - DN_) >> 1;
                        const float cc = g_cos[mr * 32 + j], ss = g_sin[mr * 32 + j];
                        const float o1 = x1 * cc - x2 * ss, o2 = x2 * cc + x1 * ss;
                        x1 = o1; x2 = o2;
                    }
                    *(uint32_t*)(outH + (size_t)mr * ldC + n) =
                        pack2h(__float2half_rn(x1), __float2half_rn(x2));
                }
            } else { // mode 2
                const int d = n & 255, hh = n >> 8;
#pragma unroll
                for (int rr = 0; rr < 2; rr++) {
                    const int mr = m + rr * 8;
                    const float x1 = acc[mf][nf][rr * 2 + 0];
                    const float x2 = acc[mf][nf][rr * 2 + 1];
                    if (d < DN_) {
                        *(uint32_t*)(outH + ((size_t)mr * NH_ + hh) * DQK_ + d) =
                            pack2h(__float2half_rn(x1), __float2half_rn(x2));
                    } else {
                        *(float2*)(vout + ((size_t)mr * NH_ + hh) * DV_ + (d - DN_)) =
                            make_float2(x1, x2);
                    }
                }
            }
        }
    }
}

// ======================= rmsnorm (fp16 output) ===============================
__global__ void rmsnorm_h(const float* __restrict__ x, int srcStride, int srcOff, int W,
                          const float* __restrict__ w, __half* __restrict__ H) {
    const int row = blockIdx.x;
    const float* xr = x + (size_t)row * srcStride + srcOff;
    float ss = 0.f;
    for (int c = threadIdx.x; c < W; c += blockDim.x) {
        float v = xr[c];
        ss += v * v;
    }
    __shared__ float red[32];
#pragma unroll
    for (int o = 16; o; o >>= 1) ss += __shfl_xor_sync(0xffffffffu, ss, o);
    if ((threadIdx.x & 31) == 0) red[threadIdx.x >> 5] = ss;
    __syncthreads();
    if (threadIdx.x < 32) {
        float v = (threadIdx.x < (blockDim.x >> 5)) ? red[threadIdx.x] : 0.f;
#pragma unroll
        for (int o = 16; o; o >>= 1) v += __shfl_xor_sync(0xffffffffu, v, o);
        red[threadIdx.x] = v;
    }
    __syncthreads();
    const float rstd = rsqrtf(red[0] / (float)W + 1e-6f);
    for (int c = threadIdx.x; c < W; c += blockDim.x)
        H[(size_t)row * W + c] = __float2half_rn(xr[c] * rstd * w[c]);
}

// ======================= RoPE tables + k_pe broadcast ========================
__global__ void rope_tab_kernel(const int* __restrict__ pos) {
    const int t = blockIdx.x, i = threadIdx.x;
    double inv = pow(10000.0, -(double)i / 32.0);
    double f = (double)pos[t] * inv;
    double s, c;
    sincos(f, &s, &c);
    g_cos[t * 32 + i] = (float)c;
    g_sin[t * 32 + i] = (float)s;
}

__global__ void kpe_build_kernel() {
    const int t = blockIdx.x;
    const int i = threadIdx.x;   // pair 0..31
    const int hh = threadIdx.y;  // 0..7
    const float c = g_cos[t * 32 + i];
    const float s = g_sin[t * 32 + i];
    const float* src = g_qkv + (size_t)t * NQKV_ + (QLR_ + KVLR_) + 2 * i;
    const float x1 = src[0], x2 = src[1];
    const uint32_t hv = pack2h(__float2half_rn(x1 * c - x2 * s),
                               __float2half_rn(x2 * c + x1 * s));
    for (int h = hh; h < NH_; h += 8)
        *(uint32_t*)(g_kh + ((size_t)t * NH_ + h) * DQK_ + DN_ + 2 * i) = hv;
}

__global__ void vtrans_kernel() {
    __shared__ float tile[32][33];
    const int t0 = blockIdx.x * 32, d0 = blockIdx.y * 32, h = blockIdx.z;
    const int tx = threadIdx.x, ty = threadIdx.y; // 32 x 8
    for (int i = ty; i < 32; i += 8)
        tile[i][tx] = g_v[((size_t)(t0 + i) * NH_ + h) * DV_ + d0 + tx];
    __syncthreads();
    for (int i = ty; i < 32; i += 8)
        g_vt[((size_t)h * DV_ + d0 + i) * T_ + t0 + tx] = __float2half_rn(tile[tx][i]);
}

// ======================= fp16 HMMA flash attention (round-6 structure) =======
#define QKP 200   // Q/K smem pitch (elems): 400B, conflict-free ldmatrix
#define PVP 72    // P/Vt pitch: 144B
#define SFP 68

struct ASmem {
    __half Q[64 * QKP];
    __half K[64 * QKP];
    __half V[128 * PVP];
    __half P[64 * PVP];
    float Sf[64 * SFP];
    float rowM[64], rowL[64], rowScale[64];
};
#define ATTN_SMEM sizeof(ASmem)

__global__ void __launch_bounds__(256, 2)
attn_mma() {
    extern __shared__ char smem_raw[];
    ASmem& sm = *(ASmem*)smem_raw;
    const int h = blockIdx.x, qb = blockIdx.y;
    const int tid = threadIdx.x, wid = tid >> 5, lane = tid & 31;
    const int wm = wid & 3, wn = wid >> 2;
    const int t0 = qb * 64;
    const int lm = lane >> 2, ln = (lane & 3) * 2;

    const uint32_t sQ = smem_u32(sm.Q);
    const uint32_t sK = smem_u32(sm.K);
    const uint32_t sV = smem_u32(sm.V);
    const uint32_t sP = smem_u32(sm.P);

    auto loadK = [&](int kc) {
        const int tk0 = kc * 64;
        for (int idx = tid; idx < 64 * 24; idx += 256) {
            const int row = idx / 24, ch = idx % 24;
            CP_ASYNC16(sK + (row * QKP + ch * 8) * 2,
                       g_kh + ((size_t)(tk0 + row) * NH_ + h) * DQK_ + ch * 8);
        }
    };
    auto loadV = [&](int kc) {
        const int tk0 = kc * 64;
        for (int idx = tid; idx < 128 * 8; idx += 256) {
            const int row = idx >> 3, ch = idx & 7;
            CP_ASYNC16(sV + (row * PVP + ch * 8) * 2,
                       g_vt + ((size_t)h * DV_ + row) * T_ + tk0 + ch * 8);
        }
    };

    // Q load (group 0), K0 (group 1), V0 (group 2)
    for (int idx = tid; idx < 64 * 24; idx += 256) {
        const int row = idx / 24, ch = idx % 24;
        CP_ASYNC16(sQ + (row * QKP + ch * 8) * 2,
                   g_qh + ((size_t)(t0 + row) * NH_ + h) * DQK_ + ch * 8);
    }
    CP_COMMIT();
    loadK(0); CP_COMMIT();
    loadV(0); CP_COMMIT();

    if (tid < 64) {
        sm.rowM[tid] = -1e30f;
        sm.rowL[tid] = 0.f;
    }

    const uint32_t aoffQ = ((wm * 16 + (lane & 15)) * QKP + ((lane >> 4) & 1) * 8) * 2;
    uint32_t boffK[4];
#pragma unroll
    for (int nf = 0; nf < 4; nf++)
        boffK[nf] = ((wn * 32 + nf * 8 + (lane & 7)) * QKP + ((lane >> 3) & 1) * 8) * 2;
    const uint32_t aoffP = ((wm * 16 + (lane & 15)) * PVP + ((lane >> 4) & 1) * 8) * 2;
    uint32_t boffV[8];
#pragma unroll
    for (int nf = 0; nf < 8; nf++)
        boffV[nf] = ((wn * 64 + nf * 8 + (lane & 7)) * PVP + ((lane >> 3) & 1) * 8) * 2;

    float accO[8][4];
#pragma unroll
    for (int i = 0; i < 8; i++)
#pragma unroll
        for (int q = 0; q < 4; q++) accO[i][q] = 0.f;

    for (int kc = 0; kc <= qb; kc++) {
        const int tk0 = kc * 64;
        CP_WAIT1();        // K(kc) ready
        __syncthreads();

        // ---- S = Q K^T ----
        float accS[4][4];
#pragma unroll
        for (int i = 0; i < 4; i++)
#pragma unroll
            for (int q = 0; q < 4; q++) accS[i][q] = 0.f;
#pragma unroll
        for (int ks = 0; ks < 12; ks++) {
            uint32_t a[4];
            LDSM_X4(a[0], a[1], a[2], a[3], sQ + aoffQ + ks * 32);
#pragma unroll
            for (int nf = 0; nf < 4; nf++) {
                uint32_t b[2];
                LDSM_X2(b[0], b[1], sK + boffK[nf] + ks * 32);
                MMA16816(accS[nf], a, b);
            }
        }
        const bool diag = (kc == qb);
#pragma unroll
        for (int nf = 0; nf < 4; nf++) {
            const int r = wm * 16 + lm;
            const int c = wn * 32 + nf * 8 + ln;
            float v0 = accS[nf][0], v1 = accS[nf][1], v2 = accS[nf][2], v3 = accS[nf][3];
            if (diag) {
                const int rg0 = t0 + r, rg1 = rg0 + 8, cg = tk0 + c;
                if (cg > rg0) v0 = -1e30f;
                if (cg + 1 > rg0) v1 = -1e30f;
                if (cg > rg1) v2 = -1e30f;
                if (cg + 1 > rg1) v3 = -1e30f;
            }
            sm.Sf[r * SFP + c] = v0;
            sm.Sf[r * SFP + c + 1] = v1;
            sm.Sf[(r + 8) * SFP + c] = v2;
            sm.Sf[(r + 8) * SFP + c + 1] = v3;
        }
        __syncthreads();   // S written; K buffer free

        if (kc < qb) { loadK(kc + 1); CP_COMMIT(); }

        // ---- online softmax ----
        {
            const int row = tid >> 2, l4 = tid & 3;
            float mloc = -1e30f;
#pragma unroll
            for (int c = 0; c < 16; c++) mloc = fmaxf(mloc, sm.Sf[row * SFP + l4 * 16 + c]);
            mloc = fmaxf(mloc, __shfl_xor_sync(0xffffffffu, mloc, 1));
            mloc = fmaxf(mloc, __shfl_xor_sync(0xffffffffu, mloc, 2));
            const float mprev = sm.rowM[row];
            const float mnew = fmaxf(mprev, mloc);
            float lsum = 0.f;
#pragma unroll
            for (int c = 0; c < 16; c += 2) {
                const int col = l4 * 16 + c;
                const float p0 = __expf(sm.Sf[row * SFP + col] - mnew);
                const float p1 = __expf(sm.Sf[row * SFP + col + 1] - mnew);
                lsum += p0 + p1;
                *(uint32_t*)(sm.P + row * PVP + col) =
                    pack2h(__float2half_rn(p0), __float2half_rn(p1));
            }
            lsum += __shfl_xor_sync(0xffffffffu, lsum, 1);
            lsum += __shfl_xor_sync(0xffffffffu, lsum, 2);
            if (l4 == 0) {
                const float sc = __expf(mprev - mnew);
                sm.rowScale[row] = sc;
                sm.rowM[row] = mnew;
                sm.rowL[row] = sm.rowL[row] * sc + lsum;
            }
        }

        // V(kc) ready (K(kc+1) may be in flight)
        if (kc < qb) { CP_WAIT1(); } else { CP_WAIT0(); }
        __syncthreads();

        // ---- rescale O, then O += P V ----
        const float s0 = sm.rowScale[wm * 16 + lm];
        const float s1 = sm.rowScale[wm * 16 + lm + 8];
#pragma unroll
        for (int nf = 0; nf < 8; nf++) {
            accO[nf][0] *= s0; accO[nf][1] *= s0;
            accO[nf][2] *= s1; accO[nf][3] *= s1;
        }
#pragma unroll
        for (int ks = 0; ks < 4; ks++) {
            uint32_t pa[4];
            LDSM_X4(pa[0], pa[1], pa[2], pa[3], sP + aoffP + ks * 32);
#pragma unroll
            for (int nf = 0; nf < 8; nf++) {
                uint32_t vb[2];
                LDSM_X2(vb[0], vb[1], sV + boffV[nf] + ks * 32);
                MMA16816(accO[nf], pa, vb);
            }
        }
        __syncthreads();   // V buffer free

        if (kc < qb) { loadV(kc + 1); CP_COMMIT(); }
    }

    // ---- finalize: /rowL -> fp16 -> g_a ----
    const float invL0 = 1.f / sm.rowL[wm * 16 + lm];
    const float invL1 = 1.f / sm.rowL[wm * 16 + lm + 8];
    const int r0g = t0 + wm * 16 + lm;
#pragma unroll
    for (int nf = 0; nf < 8; nf++) {
        const int col = h * DV_ + wn * 64 + nf * 8 + ln;
        *(uint32_t*)(g_a + (size_t)r0g * (NH_ * DV_) + col) =
            pack2h(__float2half_rn(accO[nf][0] * invL0), __float2half_rn(accO[nf][1] * invL0));
        *(uint32_t*)(g_a + (size_t)(r0g + 8) * (NH_ * DV_) + col) =
            pack2h(__float2half_rn(accO[nf][2] * invL1), __float2half_rn(accO[nf][3] * invL1));
    }
}

// ======================= launch ==============================================
extern "C" void kernel_launch(void* const* d_in, const int* in_sizes, int n_in,
                              void* d_out, int out_size) {
    const int*   positions = (const int*)d_in[0];
    const float* hidden    = (const float*)d_in[1];
    const float* w_qkv_a   = (const float*)d_in[2];
    const float* q_a_ln_w  = (const float*)d_in[3];
    const float* w_q_b     = (const float*)d_in[4];
    const float* kv_a_ln_w = (const float*)d_in[5];
    const float* w_kv_b    = (const float*)d_in[6];
    const float* w_o       = (const float*)d_in[7];
    float* out = (float*)d_out;

    float *p_qkv, *p_v;
    cudaGetSymbolAddress((void**)&p_qkv, g_qkv);
    cudaGetSymbolAddress((void**)&p_v,   g_v);

    __half *w1, *w2, *w3, *w4, *a, *qan, *kvan, *qh, *kh;
    cudaGetSymbolAddress((void**)&w1, g_w1);
    cudaGetSymbolAddress((void**)&w2, g_w2);
    cudaGetSymbolAddress((void**)&w3, g_w3);
    cudaGetSymbolAddress((void**)&w4, g_w4);
    cudaGetSymbolAddress((void**)&a,  g_a);
    cudaGetSymbolAddress((void**)&qan, g_qan);
    cudaGetSymbolAddress((void**)&kvan, g_kvan);
    cudaGetSymbolAddress((void**)&qh, g_qh);
    cudaGetSymbolAddress((void**)&kh, g_kh);

    cudaFuncSetAttribute(gemm_hmma, cudaFuncAttributeMaxDynamicSharedMemorySize, GEMM_SMEM);
    cudaFuncSetAttribute(attn_mma, cudaFuncAttributeMaxDynamicSharedMemorySize, (int)ATTN_SMEM);

    rope_tab_kernel<<<T_, 32>>>(positions);

    // weight conversions (transpose to [N,K] fp16)
    convBT_kernel<<<dim3(HID_ / 64, NQKV_PAD_ / 64), 256>>>(w_qkv_a, w1, HID_, NQKV_);
    convBT_kernel<<<dim3(QLR_ / 64, (NH_ * DQK_) / 64), 256>>>(w_q_b, w2, QLR_, NH_ * DQK_);
    convBT_kernel<<<dim3(KVLR_ / 64, (NH_ * DKV_) / 64), 256>>>(w_kv_b, w3, KVLR_, NH_ * DKV_);
    convBT_kernel<<<dim3((NH_ * DV_) / 64, HID_ / 64), 256>>>(w_o, w4, NH_ * DV_, HID_);

    // GEMM1: qkv = hidden @ w_qkv_a (fp32 out for rmsnorm + kpe)
    convA4_kernel<<<(T_ * HID_ / 4 + 255) / 256, 256>>>(hidden, a, T_ * HID_ / 4);
    gemm_hmma<<<dim3(NQKV_PAD_ / 128, T_ / 128), 256, GEMM_SMEM>>>(
        a, w1, p_qkv, NQKV_, NQKV_, HID_, 0, nullptr, nullptr);

    // rmsnorms -> fp16
    rmsnorm_h<<<T_, 256>>>(p_qkv, NQKV_, 0,    QLR_,  q_a_ln_w,  qan);
    rmsnorm_h<<<T_, 256>>>(p_qkv, NQKV_, QLR_, KVLR_, kv_a_ln_w, kvan);

    // GEMM2 (fused RoPE+scale -> qh) and GEMM3 (fused k fp16 / v fp32)
    gemm_hmma<<<dim3((NH_ * DQK_) / 128, T_ / 128), 256, GEMM_SMEM>>>(
        qan, w2, nullptr, NH_ * DQK_, NH_ * DQK_, QLR_, 1, qh, nullptr);
    gemm_hmma<<<dim3((NH_ * DKV_) / 128, T_ / 128), 256, GEMM_SMEM>>>(
        kvan, w3, nullptr, NH_ * DKV_, NH_ * DKV_, KVLR_, 2, kh, p_v);

    // k_pe broadcast + V transpose
    kpe_build_kernel<<<T_, dim3(32, 8)>>>();
    vtrans_kernel<<<dim3(T_ / 32, DV_ / 32, NH_), dim3(32, 8)>>>();

    // attention -> g_a (A operand of GEMM4)
    attn_mma<<<dim3(NH_, T_ / 64), 256, ATTN_SMEM>>>();

    // GEMM4: out = attn @ w_o
    gemm_hmma<<<dim3(HID_ / 128, T_ / 128), 256, GEMM_SMEM>>>(
        a, w4, out, HID_, HID_, NH_ * DV_, 0, nullptr, nullptr);
}

// round 9
// speedup vs baseline: 2.6007x; 1.0493x over previous
#include <cuda_runtime.h>
#include <cuda_fp16.h>
#include <math.h>
#include <stdint.h>

#define T_   1024
#define HID_ 5120
#define NH_  128
#define DN_  128
#define DR_  64
#define DV_  128
#define QLR_ 1536
#define KVLR_ 512
#define DQK_ 192    // DN+DR
#define DKV_ 256    // DN+DV
#define NQKV_ 2112  // QLR+KVLR+DR
#define NQKV_PAD_ 2304

// ---------------- fp32 scratch ----------------------------------------------
__device__ float g_qkv [T_ * NQKV_];
__device__ float g_v   [T_ * NH_ * DV_];
__device__ float g_cos [T_ * 32];
__device__ float g_sin [T_ * 32];

// ---------------- fp16 scratch ----------------------------------------------
__device__ __half g_w1[NQKV_PAD_ * HID_];
__device__ __half g_w2[(NH_*DQK_) * QLR_];
__device__ __half g_w3[(NH_*DKV_) * KVLR_];
__device__ __half g_w4[HID_ * (NH_*DV_)];
__device__ __half g_a [T_ * (NH_*DV_)];        // A buf: hidden conv, then attn out
__device__ __half g_qan[T_ * QLR_];
__device__ __half g_kvan[T_ * KVLR_];
__device__ __half g_qh[T_ * NH_ * DQK_];
__device__ __half g_kh[T_ * NH_ * DQK_];
__device__ __half g_vt[NH_ * DV_ * T_];        // [h][d][t]

// ======================= PTX helpers =========================================
__device__ __forceinline__ uint32_t smem_u32(const void* p) {
    uint32_t a;
    asm("{ .reg .u64 t; cvta.to.shared.u64 t, %1; cvt.u32.u64 %0, t; }" : "=r"(a) : "l"(p));
    return a;
}

#define CP_ASYNC16(dst_u32, src_ptr) \
    asm volatile("cp.async.cg.shared.global [%0], [%1], 16;" :: "r"(dst_u32), "l"(src_ptr))
#define CP_COMMIT() asm volatile("cp.async.commit_group;" ::: "memory")
#define CP_WAIT2()  asm volatile("cp.async.wait_group 2;" ::: "memory")
#define CP_WAIT1()  asm volatile("cp.async.wait_group 1;" ::: "memory")
#define CP_WAIT0()  asm volatile("cp.async.wait_group 0;" ::: "memory")

#define LDSM_X4(r0, r1, r2, r3, addr) \
    asm volatile("ldmatrix.sync.aligned.m8n8.x4.shared.b16 {%0,%1,%2,%3}, [%4];" \
        : "=r"(r0), "=r"(r1), "=r"(r2), "=r"(r3) : "r"(addr))
#define LDSM_X2(r0, r1, addr) \
    asm volatile("ldmatrix.sync.aligned.m8n8.x2.shared.b16 {%0,%1}, [%2];" \
        : "=r"(r0), "=r"(r1) : "r"(addr))

#define MMA16816(d, a, b) \
    asm volatile("mma.sync.aligned.m16n8k16.row.col.f32.f16.f16.f32 " \
        "{%0,%1,%2,%3},{%4,%5,%6,%7},{%8,%9},{%0,%1,%2,%3};" \
        : "+f"((d)[0]), "+f"((d)[1]), "+f"((d)[2]), "+f"((d)[3]) \
        : "r"((a)[0]), "r"((a)[1]), "r"((a)[2]), "r"((a)[3]), "r"((b)[0]), "r"((b)[1]))

// ======================= fp16 conversion =====================================
__device__ __forceinline__ uint32_t pack2h(__half a, __half b) {
    __half2 t(a, b);
    return *(uint32_t*)&t;
}

__global__ void convA4_kernel(const float* __restrict__ A,
                              __half* __restrict__ H, int n4) {
    int i = blockIdx.x * blockDim.x + threadIdx.x;
    if (i < n4) {
        float4 v = ((const float4*)A)[i];
        uint2 uh;
        uh.x = pack2h(__float2half_rn(v.x), __float2half_rn(v.y));
        uh.y = pack2h(__float2half_rn(v.z), __float2half_rn(v.w));
        ((uint2*)H)[i] = uh;
    }
}

// B [K,N] fp32 -> Bt [Npad,K] fp16 (transpose), 64x64 tiles
__global__ void convBT_kernel(const float* __restrict__ B,
                              __half* __restrict__ TH, int K, int N) {
    __shared__ float tile[64][65];
    const int k0 = blockIdx.x * 64, n0 = blockIdx.y * 64;
    const int tid = threadIdx.x; // 256
    for (int i = tid; i < 64 * 16; i += 256) {
        const int r = i >> 4, c4 = (i & 15) * 4;
        const int n = n0 + c4;
        float4 v = make_float4(0.f, 0.f, 0.f, 0.f);
        if (n < N) v = *(const float4*)(B + (size_t)(k0 + r) * N + n);
        tile[r][c4 + 0] = v.x; tile[r][c4 + 1] = v.y;
        tile[r][c4 + 2] = v.z; tile[r][c4 + 3] = v.w;
    }
    __syncthreads();
    for (int i = tid; i < 64 * 16; i += 256) {
        const int nr = i >> 4, kg = (i & 15) * 4;
        uint2 uh;
        uh.x = pack2h(__float2half_rn(tile[kg + 0][nr]), __float2half_rn(tile[kg + 1][nr]));
        uh.y = pack2h(__float2half_rn(tile[kg + 2][nr]), __float2half_rn(tile[kg + 3][nr]));
        *(uint2*)(TH + (size_t)(n0 + nr) * K + k0 + kg) = uh;
    }
}

// ======================= fp16 HMMA GEMM, BK=64, 3-stage pipeline =============
// C[M,N] = A[M,K] @ B^T[N,K], fp16 in, fp32 accum. Split-K via gridDim.z
// (mode 0 uses atomicAdd when nsplit>1; exactly 2 addends -> deterministic).
// mode 0: C fp32 | mode 1: q path (scale+RoPE->fp16) | mode 2: kv path.
#define GPITCH 144                 // 64 fp16 = 128B + 16B pad; (144/16)%8=1
#define GTILE  (128 * GPITCH)      // 18432 B
#define GSTAGE (2 * GTILE)         // 36864 B (A+B)
#define GEMM_SMEM (3 * GSTAGE)     // 110592 B

__global__ void __launch_bounds__(256, 2)
gemm_hmma(const __half* __restrict__ A, const __half* __restrict__ B,
          float* __restrict__ C, int Nreal, int ldC, int K, int mode,
          __half* __restrict__ outH, float* __restrict__ vout) {
    extern __shared__ char smem[];
    const uint32_t sb = smem_u32(smem);
    const int tid  = threadIdx.x;
    const int wid  = tid >> 5;
    const int lane = tid & 31;
    const int wm   = wid & 1;
    const int wn   = wid >> 1;
    const int bm   = blockIdx.y * 128;
    const int bn   = blockIdx.x * 128;
    const int nsplit = gridDim.z;
    const int Kpart = K / nsplit;
    const int kbase = blockIdx.z * Kpart;
    const int nchunks = Kpart >> 6;

    const int rbase = tid >> 3, c16 = tid & 7;

    auto issue = [&](int stage, int c) {
        const int k0 = kbase + (c << 6);
        const uint32_t st = sb + stage * GSTAGE;
#pragma unroll
        for (int p = 0; p < 4; p++) {
            const int row = rbase + p * 32;
            const uint32_t doff = row * GPITCH + c16 * 16;
            CP_ASYNC16(st + doff,         A + (size_t)(bm + row) * K + k0 + c16 * 8);
            CP_ASYNC16(st + GTILE + doff, B + (size_t)(bn + row) * K + k0 + c16 * 8);
        }
    };

    float acc[4][4][4];
#pragma unroll
    for (int i = 0; i < 4; i++)
#pragma unroll
        for (int j = 0; j < 4; j++)
#pragma unroll
            for (int q = 0; q < 4; q++) acc[i][j][q] = 0.f;

    uint32_t aoff[4], boff[4];
#pragma unroll
    for (int mf = 0; mf < 4; mf++) {
        const int row = wm * 64 + mf * 16 + (lane & 15);
        aoff[mf] = row * GPITCH + ((lane >> 4) & 1) * 16;
    }
#pragma unroll
    for (int nf = 0; nf < 4; nf++) {
        const int row = wn * 32 + nf * 8 + (lane & 7);
        boff[nf] = row * GPITCH + ((lane >> 3) & 1) * 16;
    }

    issue(0, 0); CP_COMMIT();
    if (nchunks > 1) issue(1, 1);
    CP_COMMIT();
    if (nchunks > 2) issue(2, 2);
    CP_COMMIT();

    int stage = 0;
    for (int c = 0; c < nchunks; c++) {
        CP_WAIT2();
        __syncthreads();
        const uint32_t st = sb + stage * GSTAGE;
#pragma unroll
        for (int ks = 0; ks < 4; ks++) {
            uint32_t a[4][4], b[4][2];
#pragma unroll
            for (int mf = 0; mf < 4; mf++)
                LDSM_X4(a[mf][0], a[mf][1], a[mf][2], a[mf][3],
                        st + aoff[mf] + ks * 32);
#pragma unroll
            for (int nf = 0; nf < 4; nf++)
                LDSM_X2(b[nf][0], b[nf][1], st + GTILE + boff[nf] + ks * 32);
#pragma unroll
            for (int mf = 0; mf < 4; mf++)
#pragma unroll
                for (int nf = 0; nf < 4; nf++)
                    MMA16816(acc[mf][nf], a[mf], b[nf]);
        }
        __syncthreads();
        if (c + 3 < nchunks) issue(stage, c + 3);
        CP_COMMIT();
        stage = (stage == 2) ? 0 : stage + 1;
    }

    const int lm = lane >> 2, ln = (lane & 3) * 2;
    const float qscale = 0.072168784f; // 1/sqrt(192)
#pragma unroll
    for (int mf = 0; mf < 4; mf++) {
#pragma unroll
        for (int nf = 0; nf < 4; nf++) {
            const int n = bn + wn * 32 + nf * 8 + ln;
            const int m = bm + wm * 64 + mf * 16 + lm;
            if (mode == 0) {
                if (n < Nreal) {
                    float* p0 = C + (size_t)m * ldC + n;
                    float* p1 = C + (size_t)(m + 8) * ldC + n;
                    if (nsplit > 1) {
                        atomicAdd(p0 + 0, acc[mf][nf][0]);
                        atomicAdd(p0 + 1, acc[mf][nf][1]);
                        atomicAdd(p1 + 0, acc[mf][nf][2]);
                        atomicAdd(p1 + 1, acc[mf][nf][3]);
                    } else {
                        p0[0] = acc[mf][nf][0]; p0[1] = acc[mf][nf][1];
                        p1[0] = acc[mf][nf][2]; p1[1] = acc[mf][nf][3];
                    }
                }
            } else if (mode == 1) {
                const int d = n % DQK_;
#pragma unroll
                for (int rr = 0; rr < 2; rr++) {
                    const int mr = m + rr * 8;
                    float x1 = acc[mf][nf][rr * 2 + 0] * qscale;
                    float x2 = acc[mf][nf][rr * 2 + 1] * qscale;
                    if (d >= DN_) {
                        const int j = (d - DN_) >> 1;
                        const float cc = g_cos[mr * 32 + j], ss = g_sin[mr * 32 + j];
                        const float o1 = x1 * cc - x2 * ss, o2 = x2 * cc + x1 * ss;
                        x1 = o1; x2 = o2;
                    }
                    *(uint32_t*)(outH + (size_t)mr * ldC + n) =
                        pack2h(__float2half_rn(x1), __float2half_rn(x2));
                }
            } else { // mode 2
                const int d = n & 255, hh = n >> 8;
#pragma unroll
                for (int rr = 0; rr < 2; rr++) {
                    const int mr = m + rr * 8;
                    const float x1 = acc[mf][nf][rr * 2 + 0];
                    const float x2 = acc[mf][nf][rr * 2 + 1];
                    if (d < DN_) {
                        *(uint32_t*)(outH + ((size_t)mr * NH_ + hh) * DQK_ + d) =
                            pack2h(__float2half_rn(x1), __float2half_rn(x2));
                    } else {
                        *(float2*)(vout + ((size_t)mr * NH_ + hh) * DV_ + (d - DN_)) =
                            make_float2(x1, x2);
                    }
                }
            }
        }
    }
}

// ======================= rmsnorm (fp16 output) ===============================
__global__ void rmsnorm_h(const float* __restrict__ x, int srcStride, int srcOff, int W,
                          const float* __restrict__ w, __half* __restrict__ H) {
    const int row = blockIdx.x;
    const float* xr = x + (size_t)row * srcStride + srcOff;
    float ss = 0.f;
    for (int c = threadIdx.x; c < W; c += blockDim.x) {
        float v = xr[c];
        ss += v * v;
    }
    __shared__ float red[32];
#pragma unroll
    for (int o = 16; o; o >>= 1) ss += __shfl_xor_sync(0xffffffffu, ss, o);
    if ((threadIdx.x & 31) == 0) red[threadIdx.x >> 5] = ss;
    __syncthreads();
    if (threadIdx.x < 32) {
        float v = (threadIdx.x < (blockDim.x >> 5)) ? red[threadIdx.x] : 0.f;
#pragma unroll
        for (int o = 16; o; o >>= 1) v += __shfl_xor_sync(0xffffffffu, v, o);
        red[threadIdx.x] = v;
    }
    __syncthreads();
    const float rstd = rsqrtf(red[0] / (float)W + 1e-6f);
    for (int c = threadIdx.x; c < W; c += blockDim.x)
        H[(size_t)row * W + c] = __float2half_rn(xr[c] * rstd * w[c]);
}

// ======================= RoPE tables + k_pe broadcast ========================
__global__ void rope_tab_kernel(const int* __restrict__ pos) {
    const int t = blockIdx.x, i = threadIdx.x;
    double inv = pow(10000.0, -(double)i / 32.0);
    double f = (double)pos[t] * inv;
    double s, c;
    sincos(f, &s, &c);
    g_cos[t * 32 + i] = (float)c;
    g_sin[t * 32 + i] = (float)s;
}

__global__ void kpe_build_kernel() {
    const int t = blockIdx.x;
    const int i = threadIdx.x;   // pair 0..31
    const int hh = threadIdx.y;  // 0..7
    const float c = g_cos[t * 32 + i];
    const float s = g_sin[t * 32 + i];
    const float* src = g_qkv + (size_t)t * NQKV_ + (QLR_ + KVLR_) + 2 * i;
    const float x1 = src[0], x2 = src[1];
    const uint32_t hv = pack2h(__float2half_rn(x1 * c - x2 * s),
                               __float2half_rn(x2 * c + x1 * s));
    for (int h = hh; h < NH_; h += 8)
        *(uint32_t*)(g_kh + ((size_t)t * NH_ + h) * DQK_ + DN_ + 2 * i) = hv;
}

__global__ void vtrans_kernel() {
    __shared__ float tile[32][33];
    const int t0 = blockIdx.x * 32, d0 = blockIdx.y * 32, h = blockIdx.z;
    const int tx = threadIdx.x, ty = threadIdx.y; // 32 x 8
    for (int i = ty; i < 32; i += 8)
        tile[i][tx] = g_v[((size_t)(t0 + i) * NH_ + h) * DV_ + d0 + tx];
    __syncthreads();
    for (int i = ty; i < 32; i += 8)
        g_vt[((size_t)h * DV_ + d0 + i) * T_ + t0 + tx] = __float2half_rn(tile[tx][i]);
}

// ======================= fp16 HMMA flash attention ===========================
#define QKP 200   // Q/K smem pitch (elems): 400B, conflict-free ldmatrix
#define PVP 72    // P/Vt pitch: 144B
#define SFP 68

struct ASmem {
    __half Q[64 * QKP];
    __half K[64 * QKP];
    __half V[128 * PVP];
    __half P[64 * PVP];
    float Sf[64 * SFP];
    float rowM[64], rowL[64], rowScale[64];
};
#define ATTN_SMEM sizeof(ASmem)

__global__ void __launch_bounds__(256, 2)
attn_mma() {
    extern __shared__ char smem_raw[];
    ASmem& sm = *(ASmem*)smem_raw;
    const int h = blockIdx.x, qb = blockIdx.y;
    const int tid = threadIdx.x, wid = tid >> 5, lane = tid & 31;
    const int wm = wid & 3, wn = wid >> 2;
    const int t0 = qb * 64;
    const int lm = lane >> 2, ln = (lane & 3) * 2;

    const uint32_t sQ = smem_u32(sm.Q);
    const uint32_t sK = smem_u32(sm.K);
    const uint32_t sV = smem_u32(sm.V);
    const uint32_t sP = smem_u32(sm.P);

    auto loadK = [&](int kc) {
        const int tk0 = kc * 64;
        for (int idx = tid; idx < 64 * 24; idx += 256) {
            const int row = idx / 24, ch = idx % 24;
            CP_ASYNC16(sK + (row * QKP + ch * 8) * 2,
                       g_kh + ((size_t)(tk0 + row) * NH_ + h) * DQK_ + ch * 8);
        }
    };
    auto loadV = [&](int kc) {
        const int tk0 = kc * 64;
        for (int idx = tid; idx < 128 * 8; idx += 256) {
            const int row = idx >> 3, ch = idx & 7;
            CP_ASYNC16(sV + (row * PVP + ch * 8) * 2,
                       g_vt + ((size_t)h * DV_ + row) * T_ + tk0 + ch * 8);
        }
    };

    for (int idx = tid; idx < 64 * 24; idx += 256) {
        const int row = idx / 24, ch = idx % 24;
        CP_ASYNC16(sQ + (row * QKP + ch * 8) * 2,
                   g_qh + ((size_t)(t0 + row) * NH_ + h) * DQK_ + ch * 8);
    }
    CP_COMMIT();
    loadK(0); CP_COMMIT();
    loadV(0); CP_COMMIT();

    if (tid < 64) {
        sm.rowM[tid] = -1e30f;
        sm.rowL[tid] = 0.f;
    }

    const uint32_t aoffQ = ((wm * 16 + (lane & 15)) * QKP + ((lane >> 4) & 1) * 8) * 2;
    uint32_t boffK[4];
#pragma unroll
    for (int nf = 0; nf < 4; nf++)
        boffK[nf] = ((wn * 32 + nf * 8 + (lane & 7)) * QKP + ((lane >> 3) & 1) * 8) * 2;
    const uint32_t aoffP = ((wm * 16 + (lane & 15)) * PVP + ((lane >> 4) & 1) * 8) * 2;
    uint32_t boffV[8];
#pragma unroll
    for (int nf = 0; nf < 8; nf++)
        boffV[nf] = ((wn * 64 + nf * 8 + (lane & 7)) * PVP + ((lane >> 3) & 1) * 8) * 2;

    float accO[8][4];
#pragma unroll
    for (int i = 0; i < 8; i++)
#pragma unroll
        for (int q = 0; q < 4; q++) accO[i][q] = 0.f;

    for (int kc = 0; kc <= qb; kc++) {
        const int tk0 = kc * 64;
        CP_WAIT1();        // K(kc) ready
        __syncthreads();

        float accS[4][4];
#pragma unroll
        for (int i = 0; i < 4; i++)
#pragma unroll
            for (int q = 0; q < 4; q++) accS[i][q] = 0.f;
#pragma unroll
        for (int ks = 0; ks < 12; ks++) {
            uint32_t a[4];
            LDSM_X4(a[0], a[1], a[2], a[3], sQ + aoffQ + ks * 32);
#pragma unroll
            for (int nf = 0; nf < 4; nf++) {
                uint32_t b[2];
                LDSM_X2(b[0], b[1], sK + boffK[nf] + ks * 32);
                MMA16816(accS[nf], a, b);
            }
        }
        const bool diag = (kc == qb);
#pragma unroll
        for (int nf = 0; nf < 4; nf++) {
            const int r = wm * 16 + lm;
            const int c = wn * 32 + nf * 8 + ln;
            float v0 = accS[nf][0], v1 = accS[nf][1], v2 = accS[nf][2], v3 = accS[nf][3];
            if (diag) {
                const int rg0 = t0 + r, rg1 = rg0 + 8, cg = tk0 + c;
                if (cg > rg0) v0 = -1e30f;
                if (cg + 1 > rg0) v1 = -1e30f;
                if (cg > rg1) v2 = -1e30f;
                if (cg + 1 > rg1) v3 = -1e30f;
            }
            sm.Sf[r * SFP + c] = v0;
            sm.Sf[r * SFP + c + 1] = v1;
            sm.Sf[(r + 8) * SFP + c] = v2;
            sm.Sf[(r + 8) * SFP + c + 1] = v3;
        }
        __syncthreads();   // S written; K buffer free

        if (kc < qb) { loadK(kc + 1); CP_COMMIT(); }

        {
            const int row = tid >> 2, l4 = tid & 3;
            float mloc = -1e30f;
#pragma unroll
            for (int c = 0; c < 16; c++) mloc = fmaxf(mloc, sm.Sf[row * SFP + l4 * 16 + c]);
            mloc = fmaxf(mloc, __shfl_xor_sync(0xffffffffu, mloc, 1));
            mloc = fmaxf(mloc, __shfl_xor_sync(0xffffffffu, mloc, 2));
            const float mprev = sm.rowM[row];
            const float mnew = fmaxf(mprev, mloc);
            float lsum = 0.f;
#pragma unroll
            for (int c = 0; c < 16; c += 2) {
                const int col = l4 * 16 + c;
                const float p0 = __expf(sm.Sf[row * SFP + col] - mnew);
                const float p1 = __expf(sm.Sf[row * SFP + col + 1] - mnew);
                lsum += p0 + p1;
                *(uint32_t*)(sm.P + row * PVP + col) =
                    pack2h(__float2half_rn(p0), __float2half_rn(p1));
            }
            lsum += __shfl_xor_sync(0xffffffffu, lsum, 1);
            lsum += __shfl_xor_sync(0xffffffffu, lsum, 2);
            if (l4 == 0) {
                const float sc = __expf(mprev - mnew);
                sm.rowScale[row] = sc;
                sm.rowM[row] = mnew;
                sm.rowL[row] = sm.rowL[row] * sc + lsum;
            }
        }

        if (kc < qb) { CP_WAIT1(); } else { CP_WAIT0(); }
        __syncthreads();

        const float s0 = sm.rowScale[wm * 16 + lm];
        const float s1 = sm.rowScale[wm * 16 + lm + 8];
#pragma unroll
        for (int nf = 0; nf < 8; nf++) {
            accO[nf][0] *= s0; accO[nf][1] *= s0;
            accO[nf][2] *= s1; accO[nf][3] *= s1;
        }
#pragma unroll
        for (int ks = 0; ks < 4; ks++) {
            uint32_t pa[4];
            LDSM_X4(pa[0], pa[1], pa[2], pa[3], sP + aoffP + ks * 32);
#pragma unroll
            for (int nf = 0; nf < 8; nf++) {
                uint32_t vb[2];
                LDSM_X2(vb[0], vb[1], sV + boffV[nf] + ks * 32);
                MMA16816(accO[nf], pa, vb);
            }
        }
        __syncthreads();

        if (kc < qb) { loadV(kc + 1); CP_COMMIT(); }
    }

    const float invL0 = 1.f / sm.rowL[wm * 16 + lm];
    const float invL1 = 1.f / sm.rowL[wm * 16 + lm + 8];
    const int r0g = t0 + wm * 16 + lm;
#pragma unroll
    for (int nf = 0; nf < 8; nf++) {
        const int col = h * DV_ + wn * 64 + nf * 8 + ln;
        *(uint32_t*)(g_a + (size_t)r0g * (NH_ * DV_) + col) =
            pack2h(__float2half_rn(accO[nf][0] * invL0), __float2half_rn(accO[nf][1] * invL0));
        *(uint32_t*)(g_a + (size_t)(r0g + 8) * (NH_ * DV_) + col) =
            pack2h(__float2half_rn(accO[nf][2] * invL1), __float2half_rn(accO[nf][3] * invL1));
    }
}

// ======================= launch ==============================================
extern "C" void kernel_launch(void* const* d_in, const int* in_sizes, int n_in,
                              void* d_out, int out_size) {
    const int*   positions = (const int*)d_in[0];
    const float* hidden    = (const float*)d_in[1];
    const float* w_qkv_a   = (const float*)d_in[2];
    const float* q_a_ln_w  = (const float*)d_in[3];
    const float* w_q_b     = (const float*)d_in[4];
    const float* kv_a_ln_w = (const float*)d_in[5];
    const float* w_kv_b    = (const float*)d_in[6];
    const float* w_o       = (const float*)d_in[7];
    float* out = (float*)d_out;

    float *p_qkv, *p_v;
    cudaGetSymbolAddress((void**)&p_qkv, g_qkv);
    cudaGetSymbolAddress((void**)&p_v,   g_v);

    __half *w1, *w2, *w3, *w4, *a, *qan, *kvan, *qh, *kh;
    cudaGetSymbolAddress((void**)&w1, g_w1);
    cudaGetSymbolAddress((void**)&w2, g_w2);
    cudaGetSymbolAddress((void**)&w3, g_w3);
    cudaGetSymbolAddress((void**)&w4, g_w4);
    cudaGetSymbolAddress((void**)&a,  g_a);
    cudaGetSymbolAddress((void**)&qan, g_qan);
    cudaGetSymbolAddress((void**)&kvan, g_kvan);
    cudaGetSymbolAddress((void**)&qh, g_qh);
    cudaGetSymbolAddress((void**)&kh, g_kh);

    cudaFuncSetAttribute(gemm_hmma, cudaFuncAttributeMaxDynamicSharedMemorySize, GEMM_SMEM);
    cudaFuncSetAttribute(attn_mma, cudaFuncAttributeMaxDynamicSharedMemorySize, (int)ATTN_SMEM);

    rope_tab_kernel<<<T_, 32>>>(positions);

    // weight conversions (transpose to [N,K] fp16)
    convBT_kernel<<<dim3(HID_ / 64, NQKV_PAD_ / 64), 256>>>(w_qkv_a, w1, HID_, NQKV_);
    convBT_kernel<<<dim3(QLR_ / 64, (NH_ * DQK_) / 64), 256>>>(w_q_b, w2, QLR_, NH_ * DQK_);
    convBT_kernel<<<dim3(KVLR_ / 64, (NH_ * DKV_) / 64), 256>>>(w_kv_b, w3, KVLR_, NH_ * DKV_);
    convBT_kernel<<<dim3((NH_ * DV_) / 64, HID_ / 64), 256>>>(w_o, w4, NH_ * DV_, HID_);

    // GEMM1: qkv = hidden @ w_qkv_a (split-K=2, atomic accumulate)
    cudaMemsetAsync(p_qkv, 0, (size_t)T_ * NQKV_ * sizeof(float));
    convA4_kernel<<<(T_ * HID_ / 4 + 255) / 256, 256>>>(hidden, a, T_ * HID_ / 4);
    gemm_hmma<<<dim3(NQKV_PAD_ / 128, T_ / 128, 2), 256, GEMM_SMEM>>>(
        a, w1, p_qkv, NQKV_, NQKV_, HID_, 0, nullptr, nullptr);

    // rmsnorms -> fp16
    rmsnorm_h<<<T_, 256>>>(p_qkv, NQKV_, 0,    QLR_,  q_a_ln_w,  qan);
    rmsnorm_h<<<T_, 256>>>(p_qkv, NQKV_, QLR_, KVLR_, kv_a_ln_w, kvan);

    // GEMM2 (fused RoPE+scale -> qh) and GEMM3 (fused k fp16 / v fp32)
    gemm_hmma<<<dim3((NH_ * DQK_) / 128, T_ / 128), 256, GEMM_SMEM>>>(
        qan, w2, nullptr, NH_ * DQK_, NH_ * DQK_, QLR_, 1, qh, nullptr);
    gemm_hmma<<<dim3((NH_ * DKV_) / 128, T_ / 128), 256, GEMM_SMEM>>>(
        kvan, w3, nullptr, NH_ * DKV_, NH_ * DKV_, KVLR_, 2, kh, p_v);

    // k_pe broadcast + V transpose
    kpe_build_kernel<<<T_, dim3(32, 8)>>>();
    vtrans_kernel<<<dim3(T_ / 32, DV_ / 32, NH_), dim3(32, 8)>>>();

    // attention -> g_a (A operand of GEMM4)
    attn_mma<<<dim3(NH_, T_ / 64), 256, ATTN_SMEM>>>();

    // GEMM4: out = attn @ w_o
    gemm_hmma<<<dim3(HID_ / 128, T_ / 128), 256, GEMM_SMEM>>>(
        a, w4, out, HID_, HID_, NH_ * DV_, 0, nullptr, nullptr);
}

// round 10
// speedup vs baseline: 2.7074x; 1.0410x over previous
#include <cuda_runtime.h>
#include <cuda_fp16.h>
#include <math.h>
#include <stdint.h>

#define T_   1024
#define HID_ 5120
#define NH_  128
#define DN_  128
#define DR_  64
#define DV_  128
#define QLR_ 1536
#define KVLR_ 512
#define DQK_ 192    // DN+DR
#define DKV_ 256    // DN+DV
#define NQKV_ 2112  // QLR+KVLR+DR
#define NQKV_PAD_ 2304

// ---------------- fp32 scratch ----------------------------------------------
__device__ float g_qkv [T_ * NQKV_];
__device__ float g_cos [T_ * 32];
__device__ float g_sin [T_ * 32];

// ---------------- fp16 scratch ----------------------------------------------
__device__ __half g_w1[HID_ * NQKV_PAD_];      // [K,N] straight-converted (padded)
__device__ __half g_w2[QLR_ * (NH_*DQK_)];
__device__ __half g_w3[KVLR_ * (NH_*DKV_)];
__device__ __half g_w4[(NH_*DV_) * HID_];
__device__ __half g_a [T_ * (NH_*DV_)];        // A buf: hidden conv, then attn out
__device__ __half g_qan[T_ * QLR_];
__device__ __half g_kvan[T_ * KVLR_];
__device__ __half g_qh[T_ * NH_ * DQK_];
__device__ __half g_kh[T_ * NH_ * DQK_];
__device__ __half g_vh[T_ * NH_ * DV_];        // V fp16 [t][h][d]

// ======================= PTX helpers =========================================
__device__ __forceinline__ uint32_t smem_u32(const void* p) {
    uint32_t a;
    asm("{ .reg .u64 t; cvta.to.shared.u64 t, %1; cvt.u32.u64 %0, t; }" : "=r"(a) : "l"(p));
    return a;
}

#define CP_ASYNC16(dst_u32, src_ptr) \
    asm volatile("cp.async.cg.shared.global [%0], [%1], 16;" :: "r"(dst_u32), "l"(src_ptr))
#define CP_COMMIT() asm volatile("cp.async.commit_group;" ::: "memory")
#define CP_WAIT2()  asm volatile("cp.async.wait_group 2;" ::: "memory")
#define CP_WAIT1()  asm volatile("cp.async.wait_group 1;" ::: "memory")
#define CP_WAIT0()  asm volatile("cp.async.wait_group 0;" ::: "memory")

#define LDSM_X4(r0, r1, r2, r3, addr) \
    asm volatile("ldmatrix.sync.aligned.m8n8.x4.shared.b16 {%0,%1,%2,%3}, [%4];" \
        : "=r"(r0), "=r"(r1), "=r"(r2), "=r"(r3) : "r"(addr))
#define LDSM_X2(r0, r1, addr) \
    asm volatile("ldmatrix.sync.aligned.m8n8.x2.shared.b16 {%0,%1}, [%2];" \
        : "=r"(r0), "=r"(r1) : "r"(addr))
#define LDSM_X4T(r0, r1, r2, r3, addr) \
    asm volatile("ldmatrix.sync.aligned.m8n8.x4.trans.shared.b16 {%0,%1,%2,%3}, [%4];" \
        : "=r"(r0), "=r"(r1), "=r"(r2), "=r"(r3) : "r"(addr))

#define MMA16816(d, a, b) \
    asm volatile("mma.sync.aligned.m16n8k16.row.col.f32.f16.f16.f32 " \
        "{%0,%1,%2,%3},{%4,%5,%6,%7},{%8,%9},{%0,%1,%2,%3};" \
        : "+f"((d)[0]), "+f"((d)[1]), "+f"((d)[2]), "+f"((d)[3]) \
        : "r"((a)[0]), "r"((a)[1]), "r"((a)[2]), "r"((a)[3]), "r"((b)[0]), "r"((b)[1]))

// ======================= fp16 conversion =====================================
__device__ __forceinline__ uint32_t pack2h(__half a, __half b) {
    __half2 t(a, b);
    return *(uint32_t*)&t;
}

__global__ void convA4_kernel(const float* __restrict__ A,
                              __half* __restrict__ H, int n4) {
    int i = blockIdx.x * blockDim.x + threadIdx.x;
    if (i < n4) {
        float4 v = ((const float4*)A)[i];
        uint2 uh;
        uh.x = pack2h(__float2half_rn(v.x), __float2half_rn(v.y));
        uh.y = pack2h(__float2half_rn(v.z), __float2half_rn(v.w));
        ((uint2*)H)[i] = uh;
    }
}

// straight-copy convert B [K,N] fp32 -> [K,Npad] fp16 (column zero-pad)
__global__ void convH_kernel(const float* __restrict__ B, __half* __restrict__ O,
                             int N, int Npad, int total8) {
    int i = blockIdx.x * blockDim.x + threadIdx.x; // unit: 8 elems
    if (i >= total8) return;
    const int npad8 = Npad >> 3;
    const int row = i / npad8;
    const int n8 = (i - row * npad8) << 3;
    uint4 o;
    if (n8 + 8 <= N) {
        const float4 v0 = *(const float4*)(B + (size_t)row * N + n8);
        const float4 v1 = *(const float4*)(B + (size_t)row * N + n8 + 4);
        o.x = pack2h(__float2half_rn(v0.x), __float2half_rn(v0.y));
        o.y = pack2h(__float2half_rn(v0.z), __float2half_rn(v0.w));
        o.z = pack2h(__float2half_rn(v1.x), __float2half_rn(v1.y));
        o.w = pack2h(__float2half_rn(v1.z), __float2half_rn(v1.w));
    } else {
        __half t[8];
#pragma unroll
        for (int j = 0; j < 8; j++)
            t[j] = (n8 + j < N) ? __float2half_rn(B[(size_t)row * N + n8 + j]) : __half(0.f);
        o.x = pack2h(t[0], t[1]); o.y = pack2h(t[2], t[3]);
        o.z = pack2h(t[4], t[5]); o.w = pack2h(t[6], t[7]);
    }
    *(uint4*)(O + ((size_t)i << 3)) = o;
}

// ======================= fp16 HMMA GEMM, B in [K,N] via trans-ldmatrix =======
// C[M,N] = A[M,K] @ B[K,N]; A fp16 [M,K] row-major, B fp16 [K,ldB].
// BK=64, 3-stage cp.async pipeline. Split-K via gridDim.z (mode 0 atomicAdd).
// mode 0: C fp32 | mode 1: q path (scale+RoPE->fp16) | mode 2: kv path.
#define APITCH 144                 // 64 fp16 = 128B + 16B pad
#define ATILE  (128 * APITCH)      // 18432 B
#define BPITCH 272                 // 128 fp16 = 256B + 16B pad; (272/16)%8=1
#define BTILE  (64 * BPITCH)       // 17408 B
#define GSTAGE (ATILE + BTILE)     // 35840 B
#define GEMM_SMEM (3 * GSTAGE)     // 107520 B

__global__ void __launch_bounds__(256, 2)
gemm_hmma(const __half* __restrict__ A, const __half* __restrict__ Bw,
          float* __restrict__ C, int Nreal, int ldC, int K, int ldB, int mode,
          __half* __restrict__ outH, __half* __restrict__ voutH) {
    extern __shared__ char smem[];
    const uint32_t sb = smem_u32(smem);
    const int tid  = threadIdx.x;
    const int wid  = tid >> 5;
    const int lane = tid & 31;
    const int wm   = wid & 1;
    const int wn   = wid >> 1;
    const int bm   = blockIdx.y * 128;
    const int bn   = blockIdx.x * 128;
    const int nsplit = gridDim.z;
    const int Kpart = K / nsplit;
    const int kbase = blockIdx.z * Kpart;
    const int nchunks = Kpart >> 6;

    auto issue = [&](int stage, int c) {
        const int k0 = kbase + (c << 6);
        const uint32_t st = sb + stage * GSTAGE;
        // A: 128 rows x 128B (8 chunks)
        {
            const int rbase = tid >> 3, c8 = tid & 7;
#pragma unroll
            for (int p = 0; p < 4; p++) {
                const int row = rbase + p * 32;
                CP_ASYNC16(st + row * APITCH + c8 * 16,
                           A + (size_t)(bm + row) * K + k0 + c8 * 8);
            }
        }
        // B: 64 k-rows x 256B (16 chunks)
        {
            const int rbase = tid >> 4, c16 = tid & 15;
#pragma unroll
            for (int p = 0; p < 4; p++) {
                const int row = rbase + p * 16;
                CP_ASYNC16(st + ATILE + row * BPITCH + c16 * 16,
                           Bw + (size_t)(k0 + row) * ldB + bn + c16 * 8);
            }
        }
    };

    float acc[4][4][4];
#pragma unroll
    for (int i = 0; i < 4; i++)
#pragma unroll
        for (int j = 0; j < 4; j++)
#pragma unroll
            for (int q = 0; q < 4; q++) acc[i][j][q] = 0.f;

    uint32_t aoff[4], boffT[2];
#pragma unroll
    for (int mf = 0; mf < 4; mf++) {
        const int row = wm * 64 + mf * 16 + (lane & 15);
        aoff[mf] = row * APITCH + ((lane >> 4) & 1) * 16;
    }
#pragma unroll
    for (int j = 0; j < 2; j++)
        boffT[j] = (lane & 15) * BPITCH + (wn * 32 + j * 16 + ((lane >> 4) & 1) * 8) * 2;

    issue(0, 0); CP_COMMIT();
    if (nchunks > 1) issue(1, 1);
    CP_COMMIT();
    if (nchunks > 2) issue(2, 2);
    CP_COMMIT();

    int stage = 0;
    for (int c = 0; c < nchunks; c++) {
        CP_WAIT2();
        __syncthreads();
        const uint32_t st = sb + stage * GSTAGE;
#pragma unroll
        for (int ks = 0; ks < 4; ks++) {
            uint32_t a[4][4], b[4][2];
#pragma unroll
            for (int mf = 0; mf < 4; mf++)
                LDSM_X4(a[mf][0], a[mf][1], a[mf][2], a[mf][3],
                        st + aoff[mf] + ks * 32);
#pragma unroll
            for (int j = 0; j < 2; j++)
                LDSM_X4T(b[2*j][0], b[2*j][1], b[2*j+1][0], b[2*j+1][1],
                         st + ATILE + boffT[j] + ks * (16 * BPITCH));
#pragma unroll
            for (int mf = 0; mf < 4; mf++)
#pragma unroll
                for (int nf = 0; nf < 4; nf++)
                    MMA16816(acc[mf][nf], a[mf], b[nf]);
        }
        __syncthreads();
        if (c + 3 < nchunks) issue(stage, c + 3);
        CP_COMMIT();
        stage = (stage == 2) ? 0 : stage + 1;
    }

    const int lm = lane >> 2, ln = (lane & 3) * 2;
    const float qscale = 0.072168784f; // 1/sqrt(192)
#pragma unroll
    for (int mf = 0; mf < 4; mf++) {
#pragma unroll
        for (int nf = 0; nf < 4; nf++) {
            const int n = bn + wn * 32 + nf * 8 + ln;
            const int m = bm + wm * 64 + mf * 16 + lm;
            if (mode == 0) {
                if (n < Nreal) {
                    float* p0 = C + (size_t)m * ldC + n;
                    float* p1 = C + (size_t)(m + 8) * ldC + n;
                    if (nsplit > 1) {
                        atomicAdd(p0 + 0, acc[mf][nf][0]);
                        atomicAdd(p0 + 1, acc[mf][nf][1]);
                        atomicAdd(p1 + 0, acc[mf][nf][2]);
                        atomicAdd(p1 + 1, acc[mf][nf][3]);
                    } else {
                        p0[0] = acc[mf][nf][0]; p0[1] = acc[mf][nf][1];
                        p1[0] = acc[mf][nf][2]; p1[1] = acc[mf][nf][3];
                    }
                }
            } else if (mode == 1) {
                const int d = n % DQK_;
#pragma unroll
                for (int rr = 0; rr < 2; rr++) {
                    const int mr = m + rr * 8;
                    float x1 = acc[mf][nf][rr * 2 + 0] * qscale;
                    float x2 = acc[mf][nf][rr * 2 + 1] * qscale;
                    if (d >= DN_) {
                        const int j = (d - DN_) >> 1;
                        const float cc = g_cos[mr * 32 + j], ss = g_sin[mr * 32 + j];
                        const float o1 = x1 * cc - x2 * ss, o2 = x2 * cc + x1 * ss;
                        x1 = o1; x2 = o2;
                    }
                    *(uint32_t*)(outH + (size_t)mr * ldC + n) =
                        pack2h(__float2half_rn(x1), __float2half_rn(x2));
                }
            } else { // mode 2
                const int d = n & 255, hh = n >> 8;
#pragma unroll
                for (int rr = 0; rr < 2; rr++) {
                    const int mr = m + rr * 8;
                    const float x1 = acc[mf][nf][rr * 2 + 0];
                    const float x2 = acc[mf][nf][rr * 2 + 1];
                    if (d < DN_) {
                        *(uint32_t*)(outH + ((size_t)mr * NH_ + hh) * DQK_ + d) =
                            pack2h(__float2half_rn(x1), __float2half_rn(x2));
                    } else {
                        *(uint32_t*)(voutH + ((size_t)mr * NH_ + hh) * DV_ + (d - DN_)) =
                            pack2h(__float2half_rn(x1), __float2half_rn(x2));
                    }
                }
            }
        }
    }
}

// ======================= rmsnorm (fp16 output) ===============================
__global__ void rmsnorm_h(const float* __restrict__ x, int srcStride, int srcOff, int W,
                          const float* __restrict__ w, __half* __restrict__ H) {
    const int row = blockIdx.x;
    const float* xr = x + (size_t)row * srcStride + srcOff;
    float ss = 0.f;
    for (int c = threadIdx.x; c < W; c += blockDim.x) {
        float v = xr[c];
        ss += v * v;
    }
    __shared__ float red[32];
#pragma unroll
    for (int o = 16; o; o >>= 1) ss += __shfl_xor_sync(0xffffffffu, ss, o);
    if ((threadIdx.x & 31) == 0) red[threadIdx.x >> 5] = ss;
    __syncthreads();
    if (threadIdx.x < 32) {
        float v = (threadIdx.x < (blockDim.x >> 5)) ? red[threadIdx.x] : 0.f;
#pragma unroll
        for (int o = 16; o; o >>= 1) v += __shfl_xor_sync(0xffffffffu, v, o);
        red[threadIdx.x] = v;
    }
    __syncthreads();
    const float rstd = rsqrtf(red[0] / (float)W + 1e-6f);
    for (int c = threadIdx.x; c < W; c += blockDim.x)
        H[(size_t)row * W + c] = __float2half_rn(xr[c] * rstd * w[c]);
}

// ======================= RoPE tables + k_pe broadcast ========================
__global__ void rope_tab_kernel(const int* __restrict__ pos) {
    const int t = blockIdx.x, i = threadIdx.x;
    double inv = pow(10000.0, -(double)i / 32.0);
    double f = (double)pos[t] * inv;
    double s, c;
    sincos(f, &s, &c);
    g_cos[t * 32 + i] = (float)c;
    g_sin[t * 32 + i] = (float)s;
}

__global__ void kpe_build_kernel() {
    const int t = blockIdx.x;
    const int i = threadIdx.x;   // pair 0..31
    const int hh = threadIdx.y;  // 0..7
    const float c = g_cos[t * 32 + i];
    const float s = g_sin[t * 32 + i];
    const float* src = g_qkv + (size_t)t * NQKV_ + (QLR_ + KVLR_) + 2 * i;
    const float x1 = src[0], x2 = src[1];
    const uint32_t hv = pack2h(__float2half_rn(x1 * c - x2 * s),
                               __float2half_rn(x2 * c + x1 * s));
    for (int h = hh; h < NH_; h += 8)
        *(uint32_t*)(g_kh + ((size_t)t * NH_ + h) * DQK_ + DN_ + 2 * i) = hv;
}

// ======================= fp16 HMMA flash attention ===========================
// V consumed in [t][h][d] layout via trans-ldmatrix (no V transpose kernel).
#define QKP 200    // Q/K pitch (elems): 400B, conflict-free ldmatrix
#define VPITCH 272 // V row pitch bytes: 256B data + 16B pad
#define PVP 72     // P pitch (elems): 144B
#define SFP 68

struct ASmem {
    __half Q[64 * QKP];
    __half K[64 * QKP];
    char  V[64 * VPITCH];
    __half P[64 * PVP];
    float Sf[64 * SFP];
    float rowM[64], rowL[64], rowScale[64];
};
#define ATTN_SMEM sizeof(ASmem)

__global__ void __launch_bounds__(256, 2)
attn_mma() {
    extern __shared__ char smem_raw[];
    ASmem& sm = *(ASmem*)smem_raw;
    const int h = blockIdx.x, qb = blockIdx.y;
    const int tid = threadIdx.x, wid = tid >> 5, lane = tid & 31;
    const int wm = wid & 3, wn = wid >> 2;
    const int t0 = qb * 64;
    const int lm = lane >> 2, ln = (lane & 3) * 2;

    const uint32_t sQ = smem_u32(sm.Q);
    const uint32_t sK = smem_u32(sm.K);
    const uint32_t sV = smem_u32(sm.V);
    const uint32_t sP = smem_u32(sm.P);

    auto loadK = [&](int kc) {
        const int tk0 = kc * 64;
        for (int idx = tid; idx < 64 * 24; idx += 256) {
            const int row = idx / 24, ch = idx % 24;
            CP_ASYNC16(sK + (row * QKP + ch * 8) * 2,
                       g_kh + ((size_t)(tk0 + row) * NH_ + h) * DQK_ + ch * 8);
        }
    };
    auto loadV = [&](int kc) {
        const int tk0 = kc * 64;
        for (int idx = tid; idx < 64 * 16; idx += 256) {
            const int row = idx >> 4, ch = idx & 15;
            CP_ASYNC16(sV + row * VPITCH + ch * 16,
                       g_vh + ((size_t)(tk0 + row) * NH_ + h) * DV_ + ch * 8);
        }
    };

    for (int idx = tid; idx < 64 * 24; idx += 256) {
        const int row = idx / 24, ch = idx % 24;
        CP_ASYNC16(sQ + (row * QKP + ch * 8) * 2,
                   g_qh + ((size_t)(t0 + row) * NH_ + h) * DQK_ + ch * 8);
    }
    CP_COMMIT();
    loadK(0); CP_COMMIT();
    loadV(0); CP_COMMIT();

    if (tid < 64) {
        sm.rowM[tid] = -1e30f;
        sm.rowL[tid] = 0.f;
    }

    const uint32_t aoffQ = ((wm * 16 + (lane & 15)) * QKP + ((lane >> 4) & 1) * 8) * 2;
    uint32_t boffK[4];
#pragma unroll
    for (int nf = 0; nf < 4; nf++)
        boffK[nf] = ((wn * 32 + nf * 8 + (lane & 7)) * QKP + ((lane >> 3) & 1) * 8) * 2;
    const uint32_t aoffP = ((wm * 16 + (lane & 15)) * PVP + ((lane >> 4) & 1) * 8) * 2;
    uint32_t voffT[4];
#pragma unroll
    for (int j = 0; j < 4; j++)
        voffT[j] = (lane & 15) * VPITCH + (wn * 64 + j * 16 + ((lane >> 4) & 1) * 8) * 2;

    float accO[8][4];
#pragma unroll
    for (int i = 0; i < 8; i++)
#pragma unroll
        for (int q = 0; q < 4; q++) accO[i][q] = 0.f;

    for (int kc = 0; kc <= qb; kc++) {
        const int tk0 = kc * 64;
        CP_WAIT1();        // K(kc) ready
        __syncthreads();

        float accS[4][4];
#pragma unroll
        for (int i = 0; i < 4; i++)
#pragma unroll
            for (int q = 0; q < 4; q++) accS[i][q] = 0.f;
#pragma unroll
        for (int ks = 0; ks < 12; ks++) {
            uint32_t a[4];
            LDSM_X4(a[0], a[1], a[2], a[3], sQ + aoffQ + ks * 32);
#pragma unroll
            for (int nf = 0; nf < 4; nf++) {
                uint32_t b[2];
                LDSM_X2(b[0], b[1], sK + boffK[nf] + ks * 32);
                MMA16816(accS[nf], a, b);
            }
        }
        const bool diag = (kc == qb);
#pragma unroll
        for (int nf = 0; nf < 4; nf++) {
            const int r = wm * 16 + lm;
            const int c = wn * 32 + nf * 8 + ln;
            float v0 = accS[nf][0], v1 = accS[nf][1], v2 = accS[nf][2], v3 = accS[nf][3];
            if (diag) {
                const int rg0 = t0 + r, rg1 = rg0 + 8, cg = tk0 + c;
                if (cg > rg0) v0 = -1e30f;
                if (cg + 1 > rg0) v1 = -1e30f;
                if (cg > rg1) v2 = -1e30f;
                if (cg + 1 > rg1) v3 = -1e30f;
            }
            sm.Sf[r * SFP + c] = v0;
            sm.Sf[r * SFP + c + 1] = v1;
            sm.Sf[(r + 8) * SFP + c] = v2;
            sm.Sf[(r + 8) * SFP + c + 1] = v3;
        }
        __syncthreads();   // S written; K buffer free

        if (kc < qb) { loadK(kc + 1); CP_COMMIT(); }

        {
            const int row = tid >> 2, l4 = tid & 3;
            float mloc = -1e30f;
#pragma unroll
            for (int c = 0; c < 16; c++) mloc = fmaxf(mloc, sm.Sf[row * SFP + l4 * 16 + c]);
            mloc = fmaxf(mloc, __shfl_xor_sync(0xffffffffu, mloc, 1));
            mloc = fmaxf(mloc, __shfl_xor_sync(0xffffffffu, mloc, 2));
            const float mprev = sm.rowM[row];
            const float mnew = fmaxf(mprev, mloc);
            float lsum = 0.f;
#pragma unroll
            for (int c = 0; c < 16; c += 2) {
                const int col = l4 * 16 + c;
                const float p0 = __expf(sm.Sf[row * SFP + col] - mnew);
                const float p1 = __expf(sm.Sf[row * SFP + col + 1] - mnew);
                lsum += p0 + p1;
                *(uint32_t*)(sm.P + row * PVP + col) =
                    pack2h(__float2half_rn(p0), __float2half_rn(p1));
            }
            lsum += __shfl_xor_sync(0xffffffffu, lsum, 1);
            lsum += __shfl_xor_sync(0xffffffffu, lsum, 2);
            if (l4 == 0) {
                const float sc = __expf(mprev - mnew);
                sm.rowScale[row] = sc;
                sm.rowM[row] = mnew;
                sm.rowL[row] = sm.rowL[row] * sc + lsum;
            }
        }

        if (kc < qb) { CP_WAIT1(); } else { CP_WAIT0(); }
        __syncthreads();

        const float s0 = sm.rowScale[wm * 16 + lm];
        const float s1 = sm.rowScale[wm * 16 + lm + 8];
#pragma unroll
        for (int nf = 0; nf < 8; nf++) {
            accO[nf][0] *= s0; accO[nf][1] *= s0;
            accO[nf][2] *= s1; accO[nf][3] *= s1;
        }
#pragma unroll
        for (int ks = 0; ks < 4; ks++) {
            uint32_t pa[4];
            LDSM_X4(pa[0], pa[1], pa[2], pa[3], sP + aoffP + ks * 32);
#pragma unroll
            for (int j = 0; j < 4; j++) {
                uint32_t vb[4];
                LDSM_X4T(vb[0], vb[1], vb[2], vb[3],
                         sV + voffT[j] + ks * (16 * VPITCH));
                MMA16816(accO[2*j],     pa, vb);
                MMA16816(accO[2*j + 1], pa, vb + 2);
            }
        }
        __syncthreads();

        if (kc < qb) { loadV(kc + 1); CP_COMMIT(); }
    }

    const float invL0 = 1.f / sm.rowL[wm * 16 + lm];
    const float invL1 = 1.f / sm.rowL[wm * 16 + lm + 8];
    const int r0g = t0 + wm * 16 + lm;
#pragma unroll
    for (int nf = 0; nf < 8; nf++) {
        const int col = h * DV_ + wn * 64 + nf * 8 + ln;
        *(uint32_t*)(g_a + (size_t)r0g * (NH_ * DV_) + col) =
            pack2h(__float2half_rn(accO[nf][0] * invL0), __float2half_rn(accO[nf][1] * invL0));
        *(uint32_t*)(g_a + (size_t)(r0g + 8) * (NH_ * DV_) + col) =
            pack2h(__float2half_rn(accO[nf][2] * invL1), __float2half_rn(accO[nf][3] * invL1));
    }
}

// ======================= launch ==============================================
extern "C" void kernel_launch(void* const* d_in, const int* in_sizes, int n_in,
                              void* d_out, int out_size) {
    const int*   positions = (const int*)d_in[0];
    const float* hidden    = (const float*)d_in[1];
    const float* w_qkv_a   = (const float*)d_in[2];
    const float* q_a_ln_w  = (const float*)d_in[3];
    const float* w_q_b     = (const float*)d_in[4];
    const float* kv_a_ln_w = (const float*)d_in[5];
    const float* w_kv_b    = (const float*)d_in[6];
    const float* w_o       = (const float*)d_in[7];
    float* out = (float*)d_out;

    float* p_qkv;
    cudaGetSymbolAddress((void**)&p_qkv, g_qkv);

    __half *w1, *w2, *w3, *w4, *a, *qan, *kvan, *qh, *kh, *vh;
    cudaGetSymbolAddress((void**)&w1, g_w1);
    cudaGetSymbolAddress((void**)&w2, g_w2);
    cudaGetSymbolAddress((void**)&w3, g_w3);
    cudaGetSymbolAddress((void**)&w4, g_w4);
    cudaGetSymbolAddress((void**)&a,  g_a);
    cudaGetSymbolAddress((void**)&qan, g_qan);
    cudaGetSymbolAddress((void**)&kvan, g_kvan);
    cudaGetSymbolAddress((void**)&qh, g_qh);
    cudaGetSymbolAddress((void**)&kh, g_kh);
    cudaGetSymbolAddress((void**)&vh, g_vh);

    cudaFuncSetAttribute(gemm_hmma, cudaFuncAttributeMaxDynamicSharedMemorySize, GEMM_SMEM);
    cudaFuncSetAttribute(attn_mma, cudaFuncAttributeMaxDynamicSharedMemorySize, (int)ATTN_SMEM);

    rope_tab_kernel<<<T_, 32>>>(positions);

    // weight conversions: straight fp32->fp16 copies (no transpose)
    {
        int t8;
        t8 = HID_ * NQKV_PAD_ / 8;
        convH_kernel<<<(t8 + 255) / 256, 256>>>(w_qkv_a, w1, NQKV_, NQKV_PAD_, t8);
        t8 = QLR_ * (NH_ * DQK_) / 8;
        convH_kernel<<<(t8 + 255) / 256, 256>>>(w_q_b, w2, NH_ * DQK_, NH_ * DQK_, t8);
        t8 = KVLR_ * (NH_ * DKV_) / 8;
        convH_kernel<<<(t8 + 255) / 256, 256>>>(w_kv_b, w3, NH_ * DKV_, NH_ * DKV_, t8);
        t8 = (NH_ * DV_) * HID_ / 8;
        convH_kernel<<<(t8 + 255) / 256, 256>>>(w_o, w4, HID_, HID_, t8);
    }

    // GEMM1: qkv = hidden @ w_qkv_a (split-K=2, atomic accumulate)
    cudaMemsetAsync(p_qkv, 0, (size_t)T_ * NQKV_ * sizeof(float));
    convA4_kernel<<<(T_ * HID_ / 4 + 255) / 256, 256>>>(hidden, a, T_ * HID_ / 4);
    gemm_hmma<<<dim3(NQKV_PAD_ / 128, T_ / 128, 2), 256, GEMM_SMEM>>>(
        a, w1, p_qkv, NQKV_, NQKV_, HID_, NQKV_PAD_, 0, nullptr, nullptr);

    // rmsnorms -> fp16
    rmsnorm_h<<<T_, 256>>>(p_qkv, NQKV_, 0,    QLR_,  q_a_ln_w,  qan);
    rmsnorm_h<<<T_, 256>>>(p_qkv, NQKV_, QLR_, KVLR_, kv_a_ln_w, kvan);

    // GEMM2 (fused RoPE+scale -> qh) and GEMM3 (fused k fp16 / v fp16)
    gemm_hmma<<<dim3((NH_ * DQK_) / 128, T_ / 128), 256, GEMM_SMEM>>>(
        qan, w2, nullptr, NH_ * DQK_, NH_ * DQK_, QLR_, NH_ * DQK_, 1, qh, nullptr);
    gemm_hmma<<<dim3((NH_ * DKV_) / 128, T_ / 128), 256, GEMM_SMEM>>>(
        kvan, w3, nullptr, NH_ * DKV_, NH_ * DKV_, KVLR_, NH_ * DKV_, 2, kh, vh);

    // k_pe broadcast
    kpe_build_kernel<<<T_, dim3(32, 8)>>>();

    // attention -> g_a (A operand of GEMM4)
    attn_mma<<<dim3(NH_, T_ / 64), 256, ATTN_SMEM>>>();

    // GEMM4: out = attn @ w_o
    gemm_hmma<<<dim3(HID_ / 128, T_ / 128), 256, GEMM_SMEM>>>(
        a, w4, out, HID_, HID_, NH_ * DV_, HID_, 0, nullptr, nullptr);
}